// round 10
// baseline (speedup 1.0000x reference)
#include <cuda_runtime.h>
#include <math.h>

#define NPAPER  100000
#define NAUTHOR 50000
#define NEDGE   400000
#define HDIM    256
#define NHEADS  8
#define HD      32

// ---------------- scratch (device globals; no allocation allowed) ----------
__device__ float g_q0[NPAPER * HDIM];
__device__ float g_k0[NAUTHOR * HDIM];
__device__ float g_v0[NAUTHOR * HDIM];
__device__ float g_q1[NAUTHOR * HDIM];
__device__ float g_k1[NPAPER * HDIM];
__device__ float g_v1[NPAPER * HDIM];
__device__ float g_q2[NPAPER * HDIM];
__device__ float g_k2[NPAPER * HDIM];
__device__ float g_v2[NPAPER * HDIM];
__device__ float g_attn0[NEDGE * NHEADS];
__device__ float g_attn1[NEDGE * NHEADS];
__device__ float g_attn2[NEDGE * NHEADS];
__device__ float g_aggw[NPAPER * HDIM];
__device__ float g_aggwr[NAUTHOR * HDIM];
__device__ float g_aggc[NPAPER * HDIM];
__device__ float g_tmp_p[NPAPER * HDIM];
__device__ float g_tmp_a[NAUTHOR * HDIM];
__device__ int   g_offs0[NPAPER + 1];
__device__ int   g_offs1[NAUTHOR + 1];
__device__ int   g_offs2[NPAPER + 1];

// ---------------- GEMM: C[M,256] = (w0*A0 + w1*A1) @ W + bias --------------
// BM=128, BN=128, BK=8, 256 threads, 8x8 register tile split 4+4,
// double-buffered smem with ONE __syncthreads per k-tile; next tile's gmem
// loads are issued before the FFMA block so their latency overlaps compute.
__global__ void __launch_bounds__(256) gemm_fused(
    const float* __restrict__ A0, const float* __restrict__ A1,
    const float* __restrict__ wsm,   // if non-null: 2-way softmax weights
    const float* __restrict__ W, const float* __restrict__ bias,
    float* __restrict__ C, int M)
{
    __shared__ float As[2][8][128];
    __shared__ float Bs[2][8][128];

    const int tid = threadIdx.x;
    const int bm = blockIdx.x * 128;
    const int bn = blockIdx.y * 128;

    float w0 = 1.f, w1 = 0.f;
    if (wsm) {
        float a = wsm[0], b = wsm[1];
        float mx = fmaxf(a, b);
        float e0 = expf(a - mx), e1 = expf(b - mx);
        float inv = 1.f / (e0 + e1);
        w0 = e0 * inv; w1 = e1 * inv;
    }

    const int tm = (tid >> 4) * 4;   // 0..60
    const int tn = (tid & 15) * 4;   // 0..60

    const int arow = tid >> 1;        // 0..127
    const int aseg = (tid & 1) * 4;   // 0 or 4
    const int brow = tid >> 5;        // 0..7
    const int bcol = (tid & 31) * 4;  // 0..124

    const bool arow_ok = (bm + arow) < M;
    const float* Arow0 = A0 + (size_t)(bm + arow) * HDIM;
    const float* Arow1 = A1 ? (A1 + (size_t)(bm + arow) * HDIM) : nullptr;

    float acc[8][8];
#pragma unroll
    for (int i = 0; i < 8; ++i)
#pragma unroll
        for (int j = 0; j < 8; ++j) acc[i][j] = 0.f;

    float4 av, bv;

    auto gload = [&](int k0) {
        av = make_float4(0.f, 0.f, 0.f, 0.f);
        if (arow_ok) {
            float4 a0 = *(const float4*)(Arow0 + k0 + aseg);
            if (Arow1) {
                float4 a1 = *(const float4*)(Arow1 + k0 + aseg);
                av = make_float4(w0 * a0.x + w1 * a1.x, w0 * a0.y + w1 * a1.y,
                                 w0 * a0.z + w1 * a1.z, w0 * a0.w + w1 * a1.w);
            } else {
                av = make_float4(w0 * a0.x, w0 * a0.y, w0 * a0.z, w0 * a0.w);
            }
        }
        bv = *(const float4*)(W + (size_t)(k0 + brow) * HDIM + bn + bcol);
    };
    auto sstore = [&](int buf) {
        As[buf][aseg + 0][arow] = av.x;
        As[buf][aseg + 1][arow] = av.y;
        As[buf][aseg + 2][arow] = av.z;
        As[buf][aseg + 3][arow] = av.w;
        *(float4*)&Bs[buf][brow][bcol] = bv;
    };

    gload(0);
    sstore(0);
    __syncthreads();

    const int T = HDIM / 8;
    for (int t = 0; t < T; ++t) {
        const int buf = t & 1;
        if (t + 1 < T) gload((t + 1) * 8);

#pragma unroll
        for (int k = 0; k < 8; ++k) {
            float a[8], b[8];
            *(float4*)(a)     = *(const float4*)&As[buf][k][tm];
            *(float4*)(a + 4) = *(const float4*)&As[buf][k][tm + 64];
            *(float4*)(b)     = *(const float4*)&Bs[buf][k][tn];
            *(float4*)(b + 4) = *(const float4*)&Bs[buf][k][tn + 64];
#pragma unroll
            for (int i = 0; i < 8; ++i)
#pragma unroll
                for (int j = 0; j < 8; ++j) acc[i][j] += a[i] * b[j];
        }

        if (t + 1 < T) {
            sstore(buf ^ 1);
            __syncthreads();
        }
    }

#pragma unroll
    for (int ih = 0; ih < 2; ++ih) {
#pragma unroll
        for (int i = 0; i < 4; ++i) {
            int row = bm + tm + ih * 64 + i;
            if (row < M) {
#pragma unroll
                for (int jh = 0; jh < 2; ++jh) {
                    int col = bn + tn + jh * 64;
                    float4 o;
                    o.x = acc[ih*4+i][jh*4+0] + bias[col + 0];
                    o.y = acc[ih*4+i][jh*4+1] + bias[col + 1];
                    o.z = acc[ih*4+i][jh*4+2] + bias[col + 2];
                    o.w = acc[ih*4+i][jh*4+3] + bias[col + 3];
                    *(float4*)&C[(size_t)row * HDIM + col] = o;
                }
            }
        }
    }
}

// ---------------- segment offsets from sorted dst --------------------------
__global__ void __launch_bounds__(256) build_offsets(
    const int* __restrict__ dst, int* __restrict__ offs, int n_dst, int E)
{
    int e = blockIdx.x * blockDim.x + threadIdx.x;
    if (e >= E) return;
    int d = dst[e];
    if (e == 0) {
        for (int k = 0; k <= d; ++k) offs[k] = 0;
    } else {
        int dp = dst[e - 1];
        for (int k = dp + 1; k <= d; ++k) offs[k] = e;
    }
    if (e == E - 1) {
        for (int k = d + 1; k <= n_dst; ++k) offs[k] = E;
    }
}

// ---------------- fused attention + aggregation: warp per dst node ---------
// pass 0: q row held in registers; per edge gather k row (pipelined), dot,
//         write attn scratch, track per-head max (clamped at 0).
// pass 1: exp/sum + V aggregation (pipelined v gather), normalize, store.
__global__ void __launch_bounds__(256) node_attn_agg(
    const float* __restrict__ q, const float* __restrict__ k,
    const float* __restrict__ v,
    const int* __restrict__ src, const int* __restrict__ offs,
    const float* __restrict__ eattn, float* __restrict__ attn,
    float* __restrict__ out, int n_dst)
{
    int node = (blockIdx.x * blockDim.x + threadIdx.x) >> 5;
    int lane = threadIdx.x & 31;
    if (node >= n_dst) return;

    int lo = offs[node];
    int hi = offs[node + 1];

    const int head = lane >> 2;   // head whose dot this lane participates in
    const int h8 = lane & 7;      // head whose softmax stats this lane tracks
    const float ea = eattn[head];

    const float4* qp = (const float4*)(q + (size_t)node * HDIM) + lane * 2;
    float4 q0 = qp[0], q1 = qp[1];

    // ---- pass 0: attention scores + max (2-stage pipelined k gather) ----
    float m = 0.f;
    float4 k0c = make_float4(0.f, 0.f, 0.f, 0.f);
    float4 k1c = make_float4(0.f, 0.f, 0.f, 0.f);
    if (lo < hi) {
        const float4* kp = (const float4*)(k + (size_t)src[lo] * HDIM) + lane * 2;
        k0c = kp[0]; k1c = kp[1];
    }
    for (int e = lo; e < hi; ++e) {
        float4 k0n = make_float4(0.f, 0.f, 0.f, 0.f);
        float4 k1n = make_float4(0.f, 0.f, 0.f, 0.f);
        if (e + 1 < hi) {
            const float4* kp = (const float4*)(k + (size_t)src[e + 1] * HDIM) + lane * 2;
            k0n = kp[0]; k1n = kp[1];
        }
        float p = q0.x * k0c.x + q0.y * k0c.y + q0.z * k0c.z + q0.w * k0c.w +
                  q1.x * k1c.x + q1.y * k1c.y + q1.z * k1c.z + q1.w * k1c.w;
        p += __shfl_xor_sync(0xffffffffu, p, 1);
        p += __shfl_xor_sync(0xffffffffu, p, 2);   // all 4 lanes hold head sum
        float val = p * 0.17677669529663687f + ea;
        if ((lane & 3) == 0) attn[(size_t)e * NHEADS + head] = val;
        float vh8 = __shfl_sync(0xffffffffu, val, h8 << 2);  // head h8's value
        m = fmaxf(m, vh8);
        k0c = k0n; k1c = k1n;
    }
    __threadfence_block();   // attn writes visible to all lanes' reads below

    // ---- pass 1: s = sum(exp), acc = sum(exp * v) (2-stage pipeline) ----
    float s = 0.f;
    float acc[8] = {0.f, 0.f, 0.f, 0.f, 0.f, 0.f, 0.f, 0.f};

    float a_cur = 0.f;
    float4 x0 = make_float4(0.f, 0.f, 0.f, 0.f);
    float4 x1 = make_float4(0.f, 0.f, 0.f, 0.f);
    if (lo < hi) {
        a_cur = attn[(size_t)lo * NHEADS + h8];
        const float4* vp = (const float4*)(v + (size_t)src[lo] * HDIM) + lane * 2;
        x0 = vp[0]; x1 = vp[1];
    }
    for (int e = lo; e < hi; ++e) {
        int en = e + 1;
        float a_nxt = 0.f;
        float4 y0 = make_float4(0.f, 0.f, 0.f, 0.f);
        float4 y1 = make_float4(0.f, 0.f, 0.f, 0.f);
        if (en < hi) {
            a_nxt = attn[(size_t)en * NHEADS + h8];
            const float4* vp = (const float4*)(v + (size_t)src[en] * HDIM) + lane * 2;
            y0 = vp[0]; y1 = vp[1];
        }
        float ev = __expf(a_cur - m);
        s += ev;
        float w = __shfl_sync(0xffffffffu, ev, head);
        acc[0] += w * x0.x; acc[1] += w * x0.y; acc[2] += w * x0.z; acc[3] += w * x0.w;
        acc[4] += w * x1.x; acc[5] += w * x1.y; acc[6] += w * x1.z; acc[7] += w * x1.w;
        a_cur = a_nxt; x0 = y0; x1 = y1;
    }
    float sh = __shfl_sync(0xffffffffu, s, head);
    float inv = 1.f / fmaxf(sh, 1e-9f);

    float* op = out + (size_t)node * HDIM + lane * 8;
    *(float4*)op       = make_float4(acc[0] * inv, acc[1] * inv, acc[2] * inv, acc[3] * inv);
    *(float4*)(op + 4) = make_float4(acc[4] * inv, acc[5] * inv, acc[6] * inv, acc[7] * inv);
}

// ---------------- residual + LayerNorm: warp per row -----------------------
__global__ void __launch_bounds__(256) ln_kernel(
    const float* __restrict__ x, const float* __restrict__ t,
    const float* __restrict__ g, const float* __restrict__ b,
    float* __restrict__ out, int M)
{
    int row = (blockIdx.x * blockDim.x + threadIdx.x) >> 5;
    int lane = threadIdx.x & 31;
    if (row >= M) return;

    const float4* xp = (const float4*)(x + (size_t)row * HDIM) + lane * 2;
    const float4* tp = (const float4*)(t + (size_t)row * HDIM) + lane * 2;
    float4 a0 = xp[0], a1 = xp[1], c0 = tp[0], c1 = tp[1];
    float vals[8];
    vals[0] = a0.x + c0.x; vals[1] = a0.y + c0.y; vals[2] = a0.z + c0.z; vals[3] = a0.w + c0.w;
    vals[4] = a1.x + c1.x; vals[5] = a1.y + c1.y; vals[6] = a1.z + c1.z; vals[7] = a1.w + c1.w;

    float sum = 0.f, sq = 0.f;
#pragma unroll
    for (int j = 0; j < 8; ++j) { sum += vals[j]; sq += vals[j] * vals[j]; }
#pragma unroll
    for (int o = 16; o; o >>= 1) {
        sum += __shfl_xor_sync(0xffffffffu, sum, o);
        sq  += __shfl_xor_sync(0xffffffffu, sq,  o);
    }
    float mean = sum * (1.f / HDIM);
    float var  = sq * (1.f / HDIM) - mean * mean;
    float inv  = rsqrtf(var + 1e-5f);

    const float4* gp = (const float4*)(g) + lane * 2;
    const float4* bp = (const float4*)(b) + lane * 2;
    float4 g0 = gp[0], g1 = gp[1], bb0 = bp[0], bb1 = bp[1];

    float* op = out + (size_t)row * HDIM + lane * 8;
    float4 o0, o1;
    o0.x = (vals[0] - mean) * inv * g0.x + bb0.x;
    o0.y = (vals[1] - mean) * inv * g0.y + bb0.y;
    o0.z = (vals[2] - mean) * inv * g0.z + bb0.z;
    o0.w = (vals[3] - mean) * inv * g0.w + bb0.w;
    o1.x = (vals[4] - mean) * inv * g1.x + bb1.x;
    o1.y = (vals[5] - mean) * inv * g1.y + bb1.y;
    o1.z = (vals[6] - mean) * inv * g1.z + bb1.z;
    o1.w = (vals[7] - mean) * inv * g1.w + bb1.w;
    *(float4*)op       = o0;
    *(float4*)(op + 4) = o1;
}

// ---------------------------------------------------------------------------
extern "C" void kernel_launch(void* const* d_in, const int* in_sizes, int n_in,
                              void* d_out, int out_size)
{
    const float* x_paper  = (const float*)d_in[0];
    const float* x_author = (const float*)d_in[1];
    const int* w_src  = (const int*)d_in[2];
    const int* w_dst  = (const int*)d_in[3];
    const int* wr_src = (const int*)d_in[4];
    const int* wr_dst = (const int*)d_in[5];
    const int* c_src  = (const int*)d_in[6];
    const int* c_dst  = (const int*)d_in[7];
    const float* Wq = (const float*)d_in[8];
    const float* bq = (const float*)d_in[9];
    const float* Wk = (const float*)d_in[10];
    const float* bk = (const float*)d_in[11];
    const float* Wv = (const float*)d_in[12];
    const float* bv = (const float*)d_in[13];
    const float* eattn = (const float*)d_in[14];
    const float* Wout_p = (const float*)d_in[15];
    const float* bout_p = (const float*)d_in[16];
    const float* Wout_a = (const float*)d_in[17];
    const float* bout_a = (const float*)d_in[18];
    const float* lng_p = (const float*)d_in[19];
    const float* lnb_p = (const float*)d_in[20];
    const float* lng_a = (const float*)d_in[21];
    const float* lnb_a = (const float*)d_in[22];
    const float* w_paper = (const float*)d_in[23];
    // d_in[24] = w_author (softmax of 1 element == 1.0, unused)

    float* out = (float*)d_out;

    float *q0, *k0, *v0, *q1, *k1, *v1, *q2, *k2, *v2;
    float *at0, *at1, *at2, *aw, *awr, *ac, *tp, *ta;
    int *of0, *of1, *of2;
    cudaGetSymbolAddress((void**)&q0, g_q0);
    cudaGetSymbolAddress((void**)&k0, g_k0);
    cudaGetSymbolAddress((void**)&v0, g_v0);
    cudaGetSymbolAddress((void**)&q1, g_q1);
    cudaGetSymbolAddress((void**)&k1, g_k1);
    cudaGetSymbolAddress((void**)&v1, g_v1);
    cudaGetSymbolAddress((void**)&q2, g_q2);
    cudaGetSymbolAddress((void**)&k2, g_k2);
    cudaGetSymbolAddress((void**)&v2, g_v2);
    cudaGetSymbolAddress((void**)&at0, g_attn0);
    cudaGetSymbolAddress((void**)&at1, g_attn1);
    cudaGetSymbolAddress((void**)&at2, g_attn2);
    cudaGetSymbolAddress((void**)&aw, g_aggw);
    cudaGetSymbolAddress((void**)&awr, g_aggwr);
    cudaGetSymbolAddress((void**)&ac, g_aggc);
    cudaGetSymbolAddress((void**)&tp, g_tmp_p);
    cudaGetSymbolAddress((void**)&ta, g_tmp_a);
    cudaGetSymbolAddress((void**)&of0, g_offs0);
    cudaGetSymbolAddress((void**)&of1, g_offs1);
    cudaGetSymbolAddress((void**)&of2, g_offs2);

    const int HH = HDIM * HDIM;

    auto gemm = [&](const float* A0, const float* A1, const float* wsm,
                    const float* W, const float* bias, float* C, int M) {
        dim3 grid((M + 127) / 128, HDIM / 128);
        gemm_fused<<<grid, 256>>>(A0, A1, wsm, W, bias, C, M);
    };

    // segment offsets
    int oblocks = (NEDGE + 255) / 256;
    build_offsets<<<oblocks, 256>>>(w_dst,  of0, NPAPER,  NEDGE);
    build_offsets<<<oblocks, 256>>>(wr_dst, of1, NAUTHOR, NEDGE);
    build_offsets<<<oblocks, 256>>>(c_dst,  of2, NPAPER,  NEDGE);

    // projections (rel 0: writes, rel 1: written_by, rel 2: cites)
    gemm(x_paper,  nullptr, nullptr, Wq + 0 * HH, bq + 0 * HDIM, q0, NPAPER);
    gemm(x_author, nullptr, nullptr, Wk + 0 * HH, bk + 0 * HDIM, k0, NAUTHOR);
    gemm(x_author, nullptr, nullptr, Wv + 0 * HH, bv + 0 * HDIM, v0, NAUTHOR);
    gemm(x_author, nullptr, nullptr, Wq + 1 * HH, bq + 1 * HDIM, q1, NAUTHOR);
    gemm(x_paper,  nullptr, nullptr, Wk + 1 * HH, bk + 1 * HDIM, k1, NPAPER);
    gemm(x_paper,  nullptr, nullptr, Wv + 1 * HH, bv + 1 * HDIM, v1, NPAPER);
    gemm(x_paper,  nullptr, nullptr, Wq + 2 * HH, bq + 2 * HDIM, q2, NPAPER);
    gemm(x_paper,  nullptr, nullptr, Wk + 2 * HH, bk + 2 * HDIM, k2, NPAPER);
    gemm(x_paper,  nullptr, nullptr, Wv + 2 * HH, bv + 2 * HDIM, v2, NPAPER);

    // fused attention + aggregation (warp per dst node)
    node_attn_agg<<<(NPAPER * 32 + 255) / 256, 256>>>(
        q0, k0, v0, w_src,  of0, eattn + 0,  at0, aw,  NPAPER);
    node_attn_agg<<<(NAUTHOR * 32 + 255) / 256, 256>>>(
        q1, k1, v1, wr_src, of1, eattn + 8,  at1, awr, NAUTHOR);
    node_attn_agg<<<(NPAPER * 32 + 255) / 256, 256>>>(
        q2, k2, v2, c_src,  of2, eattn + 16, at2, ac,  NPAPER);

    // output projections (paper combines writes+cites with softmax(w_paper))
    gemm(aw,  ac,      w_paper, Wout_p, bout_p, tp, NPAPER);
    gemm(awr, nullptr, nullptr, Wout_a, bout_a, ta, NAUTHOR);

    // residual + layernorm -> packed output [paper | author]
    ln_kernel<<<(NPAPER * 32 + 255) / 256, 256>>>(x_paper, tp, lng_p, lnb_p, out, NPAPER);
    ln_kernel<<<(NAUTHOR * 32 + 255) / 256, 256>>>(x_author, ta, lng_a, lnb_a,
                                                   out + (size_t)NPAPER * HDIM, NAUTHOR);
}

// round 12
// speedup vs baseline: 1.0423x; 1.0423x over previous
#include <cuda_runtime.h>
#include <math.h>

#define NPAPER  100000
#define NAUTHOR 50000
#define NEDGE   400000
#define HDIM    256
#define NHEADS  8
#define HD      32

// ---------------- scratch (device globals; no allocation allowed) ----------
__device__ float g_q0[NPAPER * HDIM];
__device__ float g_k0[NAUTHOR * HDIM];
__device__ float g_v0[NAUTHOR * HDIM];
__device__ float g_q1[NAUTHOR * HDIM];
__device__ float g_k1[NPAPER * HDIM];
__device__ float g_v1[NPAPER * HDIM];
__device__ float g_q2[NPAPER * HDIM];
__device__ float g_k2[NPAPER * HDIM];
__device__ float g_v2[NPAPER * HDIM];
__device__ float g_attn0[NEDGE * NHEADS];
__device__ float g_attn1[NEDGE * NHEADS];
__device__ float g_attn2[NEDGE * NHEADS];
__device__ float g_aggw[NPAPER * HDIM];
__device__ float g_aggwr[NAUTHOR * HDIM];
__device__ float g_aggc[NPAPER * HDIM];
__device__ float g_tmp_p[NPAPER * HDIM];
__device__ float g_tmp_a[NAUTHOR * HDIM];
__device__ int   g_offs0[NPAPER + 1];
__device__ int   g_offs1[NAUTHOR + 1];
__device__ int   g_offs2[NPAPER + 1];

// ---------------- GEMM: C[M,256] = (w0*A0 + w1*A1) @ W + bias --------------
// BM=128, BN=128, BK=8, 256 threads, 8x8 register tile split 4+4
// (rows {tm..tm+3, tm+64..tm+67}, cols {tn..tn+3, tn+64..tn+67}).
// Single-buffer, two syncs per k-tile — measured optimum; do not double-buffer.
__global__ void __launch_bounds__(256) gemm_fused(
    const float* __restrict__ A0, const float* __restrict__ A1,
    const float* __restrict__ wsm,   // if non-null: 2-way softmax weights
    const float* __restrict__ W, const float* __restrict__ bias,
    float* __restrict__ C, int M)
{
    __shared__ float As[8][128];
    __shared__ float Bs[8][128];

    const int tid = threadIdx.x;
    const int bm = blockIdx.x * 128;
    const int bn = blockIdx.y * 128;

    float w0 = 1.f, w1 = 0.f;
    if (wsm) {
        float a = wsm[0], b = wsm[1];
        float mx = fmaxf(a, b);
        float e0 = expf(a - mx), e1 = expf(b - mx);
        float inv = 1.f / (e0 + e1);
        w0 = e0 * inv; w1 = e1 * inv;
    }

    const int tm = (tid >> 4) * 4;   // 0..60
    const int tn = (tid & 15) * 4;   // 0..60

    const int arow = tid >> 1;        // 0..127
    const int aseg = (tid & 1) * 4;   // 0 or 4
    const int brow = tid >> 5;        // 0..7
    const int bcol = (tid & 31) * 4;  // 0..124

    const bool arow_ok = (bm + arow) < M;
    const float* Arow0 = A0 + (size_t)(bm + arow) * HDIM;
    const float* Arow1 = A1 ? (A1 + (size_t)(bm + arow) * HDIM) : nullptr;

    float acc[8][8];
#pragma unroll
    for (int i = 0; i < 8; ++i)
#pragma unroll
        for (int j = 0; j < 8; ++j) acc[i][j] = 0.f;

    for (int k0 = 0; k0 < HDIM; k0 += 8) {
        float4 av = make_float4(0.f, 0.f, 0.f, 0.f);
        if (arow_ok) {
            float4 a0 = *(const float4*)(Arow0 + k0 + aseg);
            if (Arow1) {
                float4 a1 = *(const float4*)(Arow1 + k0 + aseg);
                av = make_float4(w0 * a0.x + w1 * a1.x, w0 * a0.y + w1 * a1.y,
                                 w0 * a0.z + w1 * a1.z, w0 * a0.w + w1 * a1.w);
            } else {
                av = make_float4(w0 * a0.x, w0 * a0.y, w0 * a0.z, w0 * a0.w);
            }
        }
        float4 bv = *(const float4*)(W + (size_t)(k0 + brow) * HDIM + bn + bcol);

        __syncthreads();
        As[aseg + 0][arow] = av.x;
        As[aseg + 1][arow] = av.y;
        As[aseg + 2][arow] = av.z;
        As[aseg + 3][arow] = av.w;
        *(float4*)&Bs[brow][bcol] = bv;
        __syncthreads();

#pragma unroll
        for (int k = 0; k < 8; ++k) {
            float a[8], b[8];
            *(float4*)(a)     = *(const float4*)&As[k][tm];
            *(float4*)(a + 4) = *(const float4*)&As[k][tm + 64];
            *(float4*)(b)     = *(const float4*)&Bs[k][tn];
            *(float4*)(b + 4) = *(const float4*)&Bs[k][tn + 64];
#pragma unroll
            for (int i = 0; i < 8; ++i)
#pragma unroll
                for (int j = 0; j < 8; ++j) acc[i][j] += a[i] * b[j];
        }
    }

#pragma unroll
    for (int ih = 0; ih < 2; ++ih) {
#pragma unroll
        for (int i = 0; i < 4; ++i) {
            int row = bm + tm + ih * 64 + i;
            if (row < M) {
#pragma unroll
                for (int jh = 0; jh < 2; ++jh) {
                    int col = bn + tn + jh * 64;
                    float4 o;
                    o.x = acc[ih*4+i][jh*4+0] + bias[col + 0];
                    o.y = acc[ih*4+i][jh*4+1] + bias[col + 1];
                    o.z = acc[ih*4+i][jh*4+2] + bias[col + 2];
                    o.w = acc[ih*4+i][jh*4+3] + bias[col + 3];
                    *(float4*)&C[(size_t)row * HDIM + col] = o;
                }
            }
        }
    }
}

// ---------------- segment offsets from sorted dst --------------------------
__global__ void __launch_bounds__(256) build_offsets(
    const int* __restrict__ dst, int* __restrict__ offs, int n_dst, int E)
{
    int e = blockIdx.x * blockDim.x + threadIdx.x;
    if (e >= E) return;
    int d = dst[e];
    if (e == 0) {
        for (int k = 0; k <= d; ++k) offs[k] = 0;
    } else {
        int dp = dst[e - 1];
        for (int k = dp + 1; k <= d; ++k) offs[k] = e;
    }
    if (e == E - 1) {
        for (int k = d + 1; k <= n_dst; ++k) offs[k] = E;
    }
}

// ---------------- edge attention scores: warp per edge ---------------------
__global__ void __launch_bounds__(256) edge_attn_kernel(
    const float* __restrict__ q, const float* __restrict__ k,
    const int* __restrict__ src, const int* __restrict__ dst,
    const float* __restrict__ eattn, float* __restrict__ attn, int E)
{
    int e = (blockIdx.x * blockDim.x + threadIdx.x) >> 5;
    int lane = threadIdx.x & 31;
    if (e >= E) return;
    int s = src[e], d = dst[e];
    const float4* qp = (const float4*)(q + (size_t)d * HDIM) + lane * 2;
    const float4* kp = (const float4*)(k + (size_t)s * HDIM) + lane * 2;
    float4 q0 = qp[0], q1 = qp[1];
    float4 k0 = kp[0], k1 = kp[1];
    float p = q0.x * k0.x + q0.y * k0.y + q0.z * k0.z + q0.w * k0.w +
              q1.x * k1.x + q1.y * k1.y + q1.z * k1.z + q1.w * k1.w;
    p += __shfl_xor_sync(0xffffffffu, p, 1);
    p += __shfl_xor_sync(0xffffffffu, p, 2);
    if ((lane & 3) == 0) {
        int h = lane >> 2;
        attn[(size_t)e * NHEADS + h] = p * 0.17677669529663687f + eattn[h];
    }
}

// ---------------- segmented softmax + V aggregation: 2 warps per dst node --
// Warp-half `half` covers dims [half*128, half*128+128) = heads 4*half..4*half+3.
// Per lane: one float4 (4 dims). Stats: lane tracks head half*4 + (lane&3);
// accumulation weight for lane's dims (local head = lane>>3) fetched via
// shfl from lane (lane>>3). Pass 2 is 2-stage pipelined.
__global__ void __launch_bounds__(256) seg_agg_kernel(
    const float* __restrict__ attn, const float* __restrict__ v,
    const int* __restrict__ src, const int* __restrict__ offs,
    float* __restrict__ out, int n_dst)
{
    int wg = (blockIdx.x * blockDim.x + threadIdx.x) >> 5;   // global warp id
    int node = wg >> 1;
    int half = wg & 1;
    int lane = threadIdx.x & 31;
    if (node >= n_dst) return;

    int lo = offs[node];
    int hi = offs[node + 1];

    const int h_stat = half * 4 + (lane & 3);  // head tracked for stats (0..7)
    const int wsrc   = lane >> 3;              // lane holding this lane's weight

    // pass 1: per-head max, clamped at 0 (torch index_reduce on zeros buffer)
    float m = 0.f;
    for (int e = lo; e < hi; ++e)
        m = fmaxf(m, attn[(size_t)e * NHEADS + h_stat]);

    // pass 2: s = sum(exp), acc = sum(exp * v)  (2-stage pipeline)
    float s = 0.f;
    float acc0 = 0.f, acc1 = 0.f, acc2 = 0.f, acc3 = 0.f;

    const int dimoff = half * 128 + lane * 4;

    float a_cur = 0.f;
    float4 x = make_float4(0.f, 0.f, 0.f, 0.f);
    if (lo < hi) {
        a_cur = attn[(size_t)lo * NHEADS + h_stat];
        x = *(const float4*)(v + (size_t)src[lo] * HDIM + dimoff);
    }
    for (int e = lo; e < hi; ++e) {
        int en = e + 1;
        float a_nxt = 0.f;
        float4 y = make_float4(0.f, 0.f, 0.f, 0.f);
        if (en < hi) {
            a_nxt = attn[(size_t)en * NHEADS + h_stat];
            y = *(const float4*)(v + (size_t)src[en] * HDIM + dimoff);
        }
        float ev = __expf(a_cur - m);
        s += ev;
        float w = __shfl_sync(0xffffffffu, ev, wsrc);
        acc0 += w * x.x; acc1 += w * x.y; acc2 += w * x.z; acc3 += w * x.w;
        a_cur = a_nxt; x = y;
    }
    float sh = __shfl_sync(0xffffffffu, s, wsrc);
    float inv = 1.f / fmaxf(sh, 1e-9f);

    *(float4*)(out + (size_t)node * HDIM + dimoff) =
        make_float4(acc0 * inv, acc1 * inv, acc2 * inv, acc3 * inv);
}

// ---------------- residual + LayerNorm: warp per row -----------------------
__global__ void __launch_bounds__(256) ln_kernel(
    const float* __restrict__ x, const float* __restrict__ t,
    const float* __restrict__ g, const float* __restrict__ b,
    float* __restrict__ out, int M)
{
    int row = (blockIdx.x * blockDim.x + threadIdx.x) >> 5;
    int lane = threadIdx.x & 31;
    if (row >= M) return;

    const float4* xp = (const float4*)(x + (size_t)row * HDIM) + lane * 2;
    const float4* tp = (const float4*)(t + (size_t)row * HDIM) + lane * 2;
    float4 a0 = xp[0], a1 = xp[1], c0 = tp[0], c1 = tp[1];
    float vals[8];
    vals[0] = a0.x + c0.x; vals[1] = a0.y + c0.y; vals[2] = a0.z + c0.z; vals[3] = a0.w + c0.w;
    vals[4] = a1.x + c1.x; vals[5] = a1.y + c1.y; vals[6] = a1.z + c1.z; vals[7] = a1.w + c1.w;

    float sum = 0.f, sq = 0.f;
#pragma unroll
    for (int j = 0; j < 8; ++j) { sum += vals[j]; sq += vals[j] * vals[j]; }
#pragma unroll
    for (int o = 16; o; o >>= 1) {
        sum += __shfl_xor_sync(0xffffffffu, sum, o);
        sq  += __shfl_xor_sync(0xffffffffu, sq,  o);
    }
    float mean = sum * (1.f / HDIM);
    float var  = sq * (1.f / HDIM) - mean * mean;
    float inv  = rsqrtf(var + 1e-5f);

    const float4* gp = (const float4*)(g) + lane * 2;
    const float4* bp = (const float4*)(b) + lane * 2;
    float4 g0 = gp[0], g1 = gp[1], bb0 = bp[0], bb1 = bp[1];

    float* op = out + (size_t)row * HDIM + lane * 8;
    float4 o0, o1;
    o0.x = (vals[0] - mean) * inv * g0.x + bb0.x;
    o0.y = (vals[1] - mean) * inv * g0.y + bb0.y;
    o0.z = (vals[2] - mean) * inv * g0.z + bb0.z;
    o0.w = (vals[3] - mean) * inv * g0.w + bb0.w;
    o1.x = (vals[4] - mean) * inv * g1.x + bb1.x;
    o1.y = (vals[5] - mean) * inv * g1.y + bb1.y;
    o1.z = (vals[6] - mean) * inv * g1.z + bb1.z;
    o1.w = (vals[7] - mean) * inv * g1.w + bb1.w;
    *(float4*)op       = o0;
    *(float4*)(op + 4) = o1;
}

// ---------------------------------------------------------------------------
extern "C" void kernel_launch(void* const* d_in, const int* in_sizes, int n_in,
                              void* d_out, int out_size)
{
    const float* x_paper  = (const float*)d_in[0];
    const float* x_author = (const float*)d_in[1];
    const int* w_src  = (const int*)d_in[2];
    const int* w_dst  = (const int*)d_in[3];
    const int* wr_src = (const int*)d_in[4];
    const int* wr_dst = (const int*)d_in[5];
    const int* c_src  = (const int*)d_in[6];
    const int* c_dst  = (const int*)d_in[7];
    const float* Wq = (const float*)d_in[8];
    const float* bq = (const float*)d_in[9];
    const float* Wk = (const float*)d_in[10];
    const float* bk = (const float*)d_in[11];
    const float* Wv = (const float*)d_in[12];
    const float* bv = (const float*)d_in[13];
    const float* eattn = (const float*)d_in[14];
    const float* Wout_p = (const float*)d_in[15];
    const float* bout_p = (const float*)d_in[16];
    const float* Wout_a = (const float*)d_in[17];
    const float* bout_a = (const float*)d_in[18];
    const float* lng_p = (const float*)d_in[19];
    const float* lnb_p = (const float*)d_in[20];
    const float* lng_a = (const float*)d_in[21];
    const float* lnb_a = (const float*)d_in[22];
    const float* w_paper = (const float*)d_in[23];
    // d_in[24] = w_author (softmax of 1 element == 1.0, unused)

    float* out = (float*)d_out;

    float *q0, *k0, *v0, *q1, *k1, *v1, *q2, *k2, *v2;
    float *at0, *at1, *at2, *aw, *awr, *ac, *tp, *ta;
    int *of0, *of1, *of2;
    cudaGetSymbolAddress((void**)&q0, g_q0);
    cudaGetSymbolAddress((void**)&k0, g_k0);
    cudaGetSymbolAddress((void**)&v0, g_v0);
    cudaGetSymbolAddress((void**)&q1, g_q1);
    cudaGetSymbolAddress((void**)&k1, g_k1);
    cudaGetSymbolAddress((void**)&v1, g_v1);
    cudaGetSymbolAddress((void**)&q2, g_q2);
    cudaGetSymbolAddress((void**)&k2, g_k2);
    cudaGetSymbolAddress((void**)&v2, g_v2);
    cudaGetSymbolAddress((void**)&at0, g_attn0);
    cudaGetSymbolAddress((void**)&at1, g_attn1);
    cudaGetSymbolAddress((void**)&at2, g_attn2);
    cudaGetSymbolAddress((void**)&aw, g_aggw);
    cudaGetSymbolAddress((void**)&awr, g_aggwr);
    cudaGetSymbolAddress((void**)&ac, g_aggc);
    cudaGetSymbolAddress((void**)&tp, g_tmp_p);
    cudaGetSymbolAddress((void**)&ta, g_tmp_a);
    cudaGetSymbolAddress((void**)&of0, g_offs0);
    cudaGetSymbolAddress((void**)&of1, g_offs1);
    cudaGetSymbolAddress((void**)&of2, g_offs2);

    const int HH = HDIM * HDIM;

    auto gemm = [&](const float* A0, const float* A1, const float* wsm,
                    const float* W, const float* bias, float* C, int M) {
        dim3 grid((M + 127) / 128, HDIM / 128);
        gemm_fused<<<grid, 256>>>(A0, A1, wsm, W, bias, C, M);
    };

    // segment offsets
    int oblocks = (NEDGE + 255) / 256;
    build_offsets<<<oblocks, 256>>>(w_dst,  of0, NPAPER,  NEDGE);
    build_offsets<<<oblocks, 256>>>(wr_dst, of1, NAUTHOR, NEDGE);
    build_offsets<<<oblocks, 256>>>(c_dst,  of2, NPAPER,  NEDGE);

    // projections (rel 0: writes, rel 1: written_by, rel 2: cites)
    gemm(x_paper,  nullptr, nullptr, Wq + 0 * HH, bq + 0 * HDIM, q0, NPAPER);
    gemm(x_author, nullptr, nullptr, Wk + 0 * HH, bk + 0 * HDIM, k0, NAUTHOR);
    gemm(x_author, nullptr, nullptr, Wv + 0 * HH, bv + 0 * HDIM, v0, NAUTHOR);
    gemm(x_author, nullptr, nullptr, Wq + 1 * HH, bq + 1 * HDIM, q1, NAUTHOR);
    gemm(x_paper,  nullptr, nullptr, Wk + 1 * HH, bk + 1 * HDIM, k1, NPAPER);
    gemm(x_paper,  nullptr, nullptr, Wv + 1 * HH, bv + 1 * HDIM, v1, NPAPER);
    gemm(x_paper,  nullptr, nullptr, Wq + 2 * HH, bq + 2 * HDIM, q2, NPAPER);
    gemm(x_paper,  nullptr, nullptr, Wk + 2 * HH, bk + 2 * HDIM, k2, NPAPER);
    gemm(x_paper,  nullptr, nullptr, Wv + 2 * HH, bv + 2 * HDIM, v2, NPAPER);

    // edge attention scores (warp per edge)
    int eblocks = (NEDGE * 32 + 255) / 256;
    edge_attn_kernel<<<eblocks, 256>>>(q0, k0, w_src,  w_dst,  eattn + 0,  at0, NEDGE);
    edge_attn_kernel<<<eblocks, 256>>>(q1, k1, wr_src, wr_dst, eattn + 8,  at1, NEDGE);
    edge_attn_kernel<<<eblocks, 256>>>(q2, k2, c_src,  c_dst,  eattn + 16, at2, NEDGE);

    // segmented softmax + aggregation (2 warps per dst node)
    seg_agg_kernel<<<(NPAPER * 64 + 255) / 256, 256>>>(at0, v0, w_src,  of0, aw,  NPAPER);
    seg_agg_kernel<<<(NAUTHOR * 64 + 255) / 256, 256>>>(at1, v1, wr_src, of1, awr, NAUTHOR);
    seg_agg_kernel<<<(NPAPER * 64 + 255) / 256, 256>>>(at2, v2, c_src,  of2, ac,  NPAPER);

    // output projections (paper combines writes+cites with softmax(w_paper))
    gemm(aw,  ac,      w_paper, Wout_p, bout_p, tp, NPAPER);
    gemm(awr, nullptr, nullptr, Wout_a, bout_a, ta, NAUTHOR);

    // residual + layernorm -> packed output [paper | author]
    ln_kernel<<<(NPAPER * 32 + 255) / 256, 256>>>(x_paper, tp, lng_p, lnb_p, out, NPAPER);
    ln_kernel<<<(NAUTHOR * 32 + 255) / 256, 256>>>(x_author, ta, lng_a, lnb_a,
                                                   out + (size_t)NPAPER * HDIM, NAUTHOR);
}

// round 13
// speedup vs baseline: 1.1129x; 1.0677x over previous
#include <cuda_runtime.h>
#include <math.h>

#define NPAPER  100000
#define NAUTHOR 50000
#define NEDGE   400000
#define HDIM    256
#define NHEADS  8
#define HD      32

// ---------------- scratch (device globals; no allocation allowed) ----------
__device__ float g_q0[NPAPER * HDIM];
__device__ float g_k0[NAUTHOR * HDIM];
__device__ float g_v0[NAUTHOR * HDIM];
__device__ float g_q1[NAUTHOR * HDIM];
__device__ float g_k1[NPAPER * HDIM];
__device__ float g_v1[NPAPER * HDIM];
__device__ float g_q2[NPAPER * HDIM];
__device__ float g_k2[NPAPER * HDIM];
__device__ float g_v2[NPAPER * HDIM];
__device__ float g_attn0[NEDGE * NHEADS];
__device__ float g_attn1[NEDGE * NHEADS];
__device__ float g_attn2[NEDGE * NHEADS];
__device__ float g_aggw[NPAPER * HDIM];
__device__ float g_aggwr[NAUTHOR * HDIM];
__device__ float g_aggc[NPAPER * HDIM];
__device__ float g_tmp_p[NPAPER * HDIM];
__device__ float g_tmp_a[NAUTHOR * HDIM];
__device__ int   g_offs0[NPAPER + 1];
__device__ int   g_offs1[NAUTHOR + 1];
__device__ int   g_offs2[NPAPER + 1];

// ---------------- GEMM: C[M,256] = (w0*A0 + w1*A1) @ W + bias --------------
// BM=128, BN=128, BK=8, 256 threads, 8x8 register tile split 4+4.
// Single-buffer, two syncs per k-tile — measured optimum; do not double-buffer.
__global__ void __launch_bounds__(256) gemm_fused(
    const float* __restrict__ A0, const float* __restrict__ A1,
    const float* __restrict__ wsm,   // if non-null: 2-way softmax weights
    const float* __restrict__ W, const float* __restrict__ bias,
    float* __restrict__ C, int M)
{
    __shared__ float As[8][128];
    __shared__ float Bs[8][128];

    const int tid = threadIdx.x;
    const int bm = blockIdx.x * 128;
    const int bn = blockIdx.y * 128;

    float w0 = 1.f, w1 = 0.f;
    if (wsm) {
        float a = wsm[0], b = wsm[1];
        float mx = fmaxf(a, b);
        float e0 = expf(a - mx), e1 = expf(b - mx);
        float inv = 1.f / (e0 + e1);
        w0 = e0 * inv; w1 = e1 * inv;
    }

    const int tm = (tid >> 4) * 4;   // 0..60
    const int tn = (tid & 15) * 4;   // 0..60

    const int arow = tid >> 1;        // 0..127
    const int aseg = (tid & 1) * 4;   // 0 or 4
    const int brow = tid >> 5;        // 0..7
    const int bcol = (tid & 31) * 4;  // 0..124

    const bool arow_ok = (bm + arow) < M;
    const float* Arow0 = A0 + (size_t)(bm + arow) * HDIM;
    const float* Arow1 = A1 ? (A1 + (size_t)(bm + arow) * HDIM) : nullptr;

    float acc[8][8];
#pragma unroll
    for (int i = 0; i < 8; ++i)
#pragma unroll
        for (int j = 0; j < 8; ++j) acc[i][j] = 0.f;

    for (int k0 = 0; k0 < HDIM; k0 += 8) {
        float4 av = make_float4(0.f, 0.f, 0.f, 0.f);
        if (arow_ok) {
            float4 a0 = *(const float4*)(Arow0 + k0 + aseg);
            if (Arow1) {
                float4 a1 = *(const float4*)(Arow1 + k0 + aseg);
                av = make_float4(w0 * a0.x + w1 * a1.x, w0 * a0.y + w1 * a1.y,
                                 w0 * a0.z + w1 * a1.z, w0 * a0.w + w1 * a1.w);
            } else {
                av = make_float4(w0 * a0.x, w0 * a0.y, w0 * a0.z, w0 * a0.w);
            }
        }
        float4 bv = *(const float4*)(W + (size_t)(k0 + brow) * HDIM + bn + bcol);

        __syncthreads();
        As[aseg + 0][arow] = av.x;
        As[aseg + 1][arow] = av.y;
        As[aseg + 2][arow] = av.z;
        As[aseg + 3][arow] = av.w;
        *(float4*)&Bs[brow][bcol] = bv;
        __syncthreads();

#pragma unroll
        for (int k = 0; k < 8; ++k) {
            float a[8], b[8];
            *(float4*)(a)     = *(const float4*)&As[k][tm];
            *(float4*)(a + 4) = *(const float4*)&As[k][tm + 64];
            *(float4*)(b)     = *(const float4*)&Bs[k][tn];
            *(float4*)(b + 4) = *(const float4*)&Bs[k][tn + 64];
#pragma unroll
            for (int i = 0; i < 8; ++i)
#pragma unroll
                for (int j = 0; j < 8; ++j) acc[i][j] += a[i] * b[j];
        }
    }

#pragma unroll
    for (int ih = 0; ih < 2; ++ih) {
#pragma unroll
        for (int i = 0; i < 4; ++i) {
            int row = bm + tm + ih * 64 + i;
            if (row < M) {
#pragma unroll
                for (int jh = 0; jh < 2; ++jh) {
                    int col = bn + tn + jh * 64;
                    float4 o;
                    o.x = acc[ih*4+i][jh*4+0] + bias[col + 0];
                    o.y = acc[ih*4+i][jh*4+1] + bias[col + 1];
                    o.z = acc[ih*4+i][jh*4+2] + bias[col + 2];
                    o.w = acc[ih*4+i][jh*4+3] + bias[col + 3];
                    *(float4*)&C[(size_t)row * HDIM + col] = o;
                }
            }
        }
    }
}

// ---------------- segment offsets from sorted dst --------------------------
__global__ void __launch_bounds__(256) build_offsets(
    const int* __restrict__ dst, int* __restrict__ offs, int n_dst, int E)
{
    int e = blockIdx.x * blockDim.x + threadIdx.x;
    if (e >= E) return;
    int d = dst[e];
    if (e == 0) {
        for (int k = 0; k <= d; ++k) offs[k] = 0;
    } else {
        int dp = dst[e - 1];
        for (int k = dp + 1; k <= d; ++k) offs[k] = e;
    }
    if (e == E - 1) {
        for (int k = d + 1; k <= n_dst; ++k) offs[k] = E;
    }
}

// ---------------- edge attention scores: warp per edge ---------------------
__global__ void __launch_bounds__(256) edge_attn_kernel(
    const float* __restrict__ q, const float* __restrict__ k,
    const int* __restrict__ src, const int* __restrict__ dst,
    const float* __restrict__ eattn, float* __restrict__ attn, int E)
{
    int e = (blockIdx.x * blockDim.x + threadIdx.x) >> 5;
    int lane = threadIdx.x & 31;
    if (e >= E) return;
    int s = src[e], d = dst[e];
    const float4* qp = (const float4*)(q + (size_t)d * HDIM) + lane * 2;
    const float4* kp = (const float4*)(k + (size_t)s * HDIM) + lane * 2;
    float4 q0 = qp[0], q1 = qp[1];
    float4 k0 = kp[0], k1 = kp[1];
    float p = q0.x * k0.x + q0.y * k0.y + q0.z * k0.z + q0.w * k0.w +
              q1.x * k1.x + q1.y * k1.y + q1.z * k1.z + q1.w * k1.w;
    p += __shfl_xor_sync(0xffffffffu, p, 1);
    p += __shfl_xor_sync(0xffffffffu, p, 2);
    if ((lane & 3) == 0) {
        int h = lane >> 2;
        attn[(size_t)e * NHEADS + h] = p * 0.17677669529663687f + eattn[h];
    }
}

// ---------------- segmented softmax + V aggregation: warp per dst node -----
// pass 2 is software-pipelined (2-stage).
__global__ void __launch_bounds__(256) seg_agg_kernel(
    const float* __restrict__ attn, const float* __restrict__ v,
    const int* __restrict__ src, const int* __restrict__ offs,
    float* __restrict__ out, int n_dst)
{
    int node = (blockIdx.x * blockDim.x + threadIdx.x) >> 5;
    int lane = threadIdx.x & 31;
    if (node >= n_dst) return;

    int lo = offs[node];
    int hi = offs[node + 1];

    const int h8 = lane & 7;
    const int head = lane >> 2;

    // pass 1: per-head max, clamped at 0 (torch index_reduce on zeros buffer)
    float m = 0.f;
    for (int e = lo; e < hi; ++e)
        m = fmaxf(m, attn[(size_t)e * NHEADS + h8]);

    // pass 2: s = sum(exp), acc = sum(exp * v)
    float s = 0.f;
    float acc[8] = {0.f, 0.f, 0.f, 0.f, 0.f, 0.f, 0.f, 0.f};

    float a_cur = 0.f;
    float4 x0 = make_float4(0.f, 0.f, 0.f, 0.f);
    float4 x1 = make_float4(0.f, 0.f, 0.f, 0.f);
    if (lo < hi) {
        a_cur = attn[(size_t)lo * NHEADS + h8];
        const float4* vp = (const float4*)(v + (size_t)src[lo] * HDIM) + lane * 2;
        x0 = vp[0]; x1 = vp[1];
    }
    for (int e = lo; e < hi; ++e) {
        int en = e + 1;
        float a_nxt = 0.f;
        float4 y0 = make_float4(0.f, 0.f, 0.f, 0.f);
        float4 y1 = make_float4(0.f, 0.f, 0.f, 0.f);
        if (en < hi) {
            a_nxt = attn[(size_t)en * NHEADS + h8];
            const float4* vp = (const float4*)(v + (size_t)src[en] * HDIM) + lane * 2;
            y0 = vp[0]; y1 = vp[1];
        }
        float ev = __expf(a_cur - m);
        s += ev;
        float w = __shfl_sync(0xffffffffu, ev, head);
        acc[0] += w * x0.x; acc[1] += w * x0.y; acc[2] += w * x0.z; acc[3] += w * x0.w;
        acc[4] += w * x1.x; acc[5] += w * x1.y; acc[6] += w * x1.z; acc[7] += w * x1.w;
        a_cur = a_nxt; x0 = y0; x1 = y1;
    }
    float sh = __shfl_sync(0xffffffffu, s, head);
    float inv = 1.f / fmaxf(sh, 1e-9f);

    float* op = out + (size_t)node * HDIM + lane * 8;
    *(float4*)op       = make_float4(acc[0] * inv, acc[1] * inv, acc[2] * inv, acc[3] * inv);
    *(float4*)(op + 4) = make_float4(acc[4] * inv, acc[5] * inv, acc[6] * inv, acc[7] * inv);
}

// ---------------- residual + LayerNorm: warp per row -----------------------
__global__ void __launch_bounds__(256) ln_kernel(
    const float* __restrict__ x, const float* __restrict__ t,
    const float* __restrict__ g, const float* __restrict__ b,
    float* __restrict__ out, int M)
{
    int row = (blockIdx.x * blockDim.x + threadIdx.x) >> 5;
    int lane = threadIdx.x & 31;
    if (row >= M) return;

    const float4* xp = (const float4*)(x + (size_t)row * HDIM) + lane * 2;
    const float4* tp = (const float4*)(t + (size_t)row * HDIM) + lane * 2;
    float4 a0 = xp[0], a1 = xp[1], c0 = tp[0], c1 = tp[1];
    float vals[8];
    vals[0] = a0.x + c0.x; vals[1] = a0.y + c0.y; vals[2] = a0.z + c0.z; vals[3] = a0.w + c0.w;
    vals[4] = a1.x + c1.x; vals[5] = a1.y + c1.y; vals[6] = a1.z + c1.z; vals[7] = a1.w + c1.w;

    float sum = 0.f, sq = 0.f;
#pragma unroll
    for (int j = 0; j < 8; ++j) { sum += vals[j]; sq += vals[j] * vals[j]; }
#pragma unroll
    for (int o = 16; o; o >>= 1) {
        sum += __shfl_xor_sync(0xffffffffu, sum, o);
        sq  += __shfl_xor_sync(0xffffffffu, sq,  o);
    }
    float mean = sum * (1.f / HDIM);
    float var  = sq * (1.f / HDIM) - mean * mean;
    float inv  = rsqrtf(var + 1e-5f);

    const float4* gp = (const float4*)(g) + lane * 2;
    const float4* bp = (const float4*)(b) + lane * 2;
    float4 g0 = gp[0], g1 = gp[1], bb0 = bp[0], bb1 = bp[1];

    float* op = out + (size_t)row * HDIM + lane * 8;
    float4 o0, o1;
    o0.x = (vals[0] - mean) * inv * g0.x + bb0.x;
    o0.y = (vals[1] - mean) * inv * g0.y + bb0.y;
    o0.z = (vals[2] - mean) * inv * g0.z + bb0.z;
    o0.w = (vals[3] - mean) * inv * g0.w + bb0.w;
    o1.x = (vals[4] - mean) * inv * g1.x + bb1.x;
    o1.y = (vals[5] - mean) * inv * g1.y + bb1.y;
    o1.z = (vals[6] - mean) * inv * g1.z + bb1.z;
    o1.w = (vals[7] - mean) * inv * g1.w + bb1.w;
    *(float4*)op       = o0;
    *(float4*)(op + 4) = o1;
}

// ---------------------------------------------------------------------------
extern "C" void kernel_launch(void* const* d_in, const int* in_sizes, int n_in,
                              void* d_out, int out_size)
{
    const float* x_paper  = (const float*)d_in[0];
    const float* x_author = (const float*)d_in[1];
    const int* w_src  = (const int*)d_in[2];
    const int* w_dst  = (const int*)d_in[3];
    const int* wr_src = (const int*)d_in[4];
    const int* wr_dst = (const int*)d_in[5];
    const int* c_src  = (const int*)d_in[6];
    const int* c_dst  = (const int*)d_in[7];
    const float* Wq = (const float*)d_in[8];
    const float* bq = (const float*)d_in[9];
    const float* Wk = (const float*)d_in[10];
    const float* bk = (const float*)d_in[11];
    const float* Wv = (const float*)d_in[12];
    const float* bv = (const float*)d_in[13];
    const float* eattn = (const float*)d_in[14];
    const float* Wout_p = (const float*)d_in[15];
    const float* bout_p = (const float*)d_in[16];
    const float* Wout_a = (const float*)d_in[17];
    const float* bout_a = (const float*)d_in[18];
    const float* lng_p = (const float*)d_in[19];
    const float* lnb_p = (const float*)d_in[20];
    const float* lng_a = (const float*)d_in[21];
    const float* lnb_a = (const float*)d_in[22];
    const float* w_paper = (const float*)d_in[23];
    // d_in[24] = w_author (softmax of 1 element == 1.0, unused)

    float* out = (float*)d_out;

    float *q0, *k0, *v0, *q1, *k1, *v1, *q2, *k2, *v2;
    float *at0, *at1, *at2, *aw, *awr, *ac, *tp, *ta;
    int *of0, *of1, *of2;
    cudaGetSymbolAddress((void**)&q0, g_q0);
    cudaGetSymbolAddress((void**)&k0, g_k0);
    cudaGetSymbolAddress((void**)&v0, g_v0);
    cudaGetSymbolAddress((void**)&q1, g_q1);
    cudaGetSymbolAddress((void**)&k1, g_k1);
    cudaGetSymbolAddress((void**)&v1, g_v1);
    cudaGetSymbolAddress((void**)&q2, g_q2);
    cudaGetSymbolAddress((void**)&k2, g_k2);
    cudaGetSymbolAddress((void**)&v2, g_v2);
    cudaGetSymbolAddress((void**)&at0, g_attn0);
    cudaGetSymbolAddress((void**)&at1, g_attn1);
    cudaGetSymbolAddress((void**)&at2, g_attn2);
    cudaGetSymbolAddress((void**)&aw, g_aggw);
    cudaGetSymbolAddress((void**)&awr, g_aggwr);
    cudaGetSymbolAddress((void**)&ac, g_aggc);
    cudaGetSymbolAddress((void**)&tp, g_tmp_p);
    cudaGetSymbolAddress((void**)&ta, g_tmp_a);
    cudaGetSymbolAddress((void**)&of0, g_offs0);
    cudaGetSymbolAddress((void**)&of1, g_offs1);
    cudaGetSymbolAddress((void**)&of2, g_offs2);

    const int HH = HDIM * HDIM;

    auto gemm = [&](const float* A0, const float* A1, const float* wsm,
                    const float* W, const float* bias, float* C, int M) {
        dim3 grid((M + 127) / 128, HDIM / 128);
        gemm_fused<<<grid, 256>>>(A0, A1, wsm, W, bias, C, M);
    };

    // ---- side stream + fork/join events (created per call; NOT destroyed
    // while capture is in progress — a handful of handles per call is the
    // price of keeping the captured graph valid) ----
    cudaStream_t s2;
    cudaStreamCreateWithFlags(&s2, cudaStreamNonBlocking);
    cudaEvent_t evStart, evA, evB, evC, evDone;
    cudaEventCreateWithFlags(&evStart, cudaEventDisableTiming);
    cudaEventCreateWithFlags(&evA,     cudaEventDisableTiming);
    cudaEventCreateWithFlags(&evB,     cudaEventDisableTiming);
    cudaEventCreateWithFlags(&evC,     cudaEventDisableTiming);
    cudaEventCreateWithFlags(&evDone,  cudaEventDisableTiming);

    // fork: side stream joins the capture via evStart
    cudaEventRecord(evStart, 0);
    cudaStreamWaitEvent(s2, evStart, 0);

    // side stream: offset builds (depend only on harness inputs)
    int oblocks = (NEDGE + 255) / 256;
    build_offsets<<<oblocks, 256, 0, s2>>>(w_dst,  of0, NPAPER,  NEDGE);
    build_offsets<<<oblocks, 256, 0, s2>>>(wr_dst, of1, NAUTHOR, NEDGE);
    build_offsets<<<oblocks, 256, 0, s2>>>(c_dst,  of2, NPAPER,  NEDGE);

    // main stream: rel-0 projections, then signal
    gemm(x_paper,  nullptr, nullptr, Wq + 0 * HH, bq + 0 * HDIM, q0, NPAPER);
    gemm(x_author, nullptr, nullptr, Wk + 0 * HH, bk + 0 * HDIM, k0, NAUTHOR);
    gemm(x_author, nullptr, nullptr, Wv + 0 * HH, bv + 0 * HDIM, v0, NAUTHOR);
    cudaEventRecord(evA, 0);

    // main stream: rel-1 projections, then signal
    gemm(x_author, nullptr, nullptr, Wq + 1 * HH, bq + 1 * HDIM, q1, NAUTHOR);
    gemm(x_paper,  nullptr, nullptr, Wk + 1 * HH, bk + 1 * HDIM, k1, NPAPER);
    gemm(x_paper,  nullptr, nullptr, Wv + 1 * HH, bv + 1 * HDIM, v1, NPAPER);
    cudaEventRecord(evB, 0);

    // main stream: rel-2 projections, then signal
    gemm(x_paper,  nullptr, nullptr, Wq + 2 * HH, bq + 2 * HDIM, q2, NPAPER);
    gemm(x_paper,  nullptr, nullptr, Wk + 2 * HH, bk + 2 * HDIM, k2, NPAPER);
    gemm(x_paper,  nullptr, nullptr, Wv + 2 * HH, bv + 2 * HDIM, v2, NPAPER);
    cudaEventRecord(evC, 0);

    // side stream: per-relation edge phase as soon as its projections land
    int eblocks = (NEDGE * 32 + 255) / 256;
    cudaStreamWaitEvent(s2, evA, 0);
    edge_attn_kernel<<<eblocks, 256, 0, s2>>>(q0, k0, w_src,  w_dst,  eattn + 0,  at0, NEDGE);
    seg_agg_kernel<<<(NPAPER * 32 + 255) / 256, 256, 0, s2>>>(at0, v0, w_src,  of0, aw,  NPAPER);
    cudaStreamWaitEvent(s2, evB, 0);
    edge_attn_kernel<<<eblocks, 256, 0, s2>>>(q1, k1, wr_src, wr_dst, eattn + 8,  at1, NEDGE);
    seg_agg_kernel<<<(NAUTHOR * 32 + 255) / 256, 256, 0, s2>>>(at1, v1, wr_src, of1, awr, NAUTHOR);
    cudaStreamWaitEvent(s2, evC, 0);
    edge_attn_kernel<<<eblocks, 256, 0, s2>>>(q2, k2, c_src,  c_dst,  eattn + 16, at2, NEDGE);
    seg_agg_kernel<<<(NPAPER * 32 + 255) / 256, 256, 0, s2>>>(at2, v2, c_src,  of2, ac,  NPAPER);
    cudaEventRecord(evDone, s2);

    // join: main stream waits for aggregation outputs
    cudaStreamWaitEvent(0, evDone, 0);

    // output projections (paper combines writes+cites with softmax(w_paper))
    gemm(aw,  ac,      w_paper, Wout_p, bout_p, tp, NPAPER);
    gemm(awr, nullptr, nullptr, Wout_a, bout_a, ta, NAUTHOR);

    // residual + layernorm -> packed output [paper | author]
    ln_kernel<<<(NPAPER * 32 + 255) / 256, 256>>>(x_paper, tp, lng_p, lnb_p, out, NPAPER);
    ln_kernel<<<(NAUTHOR * 32 + 255) / 256, 256>>>(x_author, ta, lng_a, lnb_a,
                                                   out + (size_t)NPAPER * HDIM, NAUTHOR);
}

// round 14
// speedup vs baseline: 2.0335x; 1.8271x over previous
#include <cuda_runtime.h>
#include <cuda_bf16.h>
#include <math.h>
#include <stdint.h>

#define NPAPER  100000
#define NAUTHOR 50000
#define NEDGE   400000
#define HDIM    256
#define NHEADS  8
#define HD      32

// ---------------- scratch (device globals; no allocation allowed) ----------
__device__ float g_q0[NPAPER * HDIM];
__device__ float g_k0[NAUTHOR * HDIM];
__device__ float g_v0[NAUTHOR * HDIM];
__device__ float g_q1[NAUTHOR * HDIM];
__device__ float g_k1[NPAPER * HDIM];
__device__ float g_v1[NPAPER * HDIM];
__device__ float g_q2[NPAPER * HDIM];
__device__ float g_k2[NPAPER * HDIM];
__device__ float g_v2[NPAPER * HDIM];
__device__ float g_attn0[NEDGE * NHEADS];
__device__ float g_attn1[NEDGE * NHEADS];
__device__ float g_attn2[NEDGE * NHEADS];
__device__ float g_aggw[NPAPER * HDIM];
__device__ float g_aggwr[NAUTHOR * HDIM];
__device__ float g_aggc[NPAPER * HDIM];
__device__ float g_tmp_p[NPAPER * HDIM];
__device__ float g_tmp_a[NAUTHOR * HDIM];
__device__ int   g_offs0[NPAPER + 1];
__device__ int   g_offs1[NAUTHOR + 1];
__device__ int   g_offs2[NPAPER + 1];

// split-bf16 operands
__device__ __nv_bfloat16 g_xp_hi[NPAPER * HDIM];
__device__ __nv_bfloat16 g_xp_lo[NPAPER * HDIM];
__device__ __nv_bfloat16 g_xa_hi[NAUTHOR * HDIM];
__device__ __nv_bfloat16 g_xa_lo[NAUTHOR * HDIM];
__device__ __nv_bfloat16 g_cb_hi[NPAPER * HDIM];
__device__ __nv_bfloat16 g_cb_lo[NPAPER * HDIM];
__device__ __nv_bfloat16 g_ar_hi[NAUTHOR * HDIM];
__device__ __nv_bfloat16 g_ar_lo[NAUTHOR * HDIM];
__device__ __nv_bfloat16 g_w_hi[11 * HDIM * HDIM];
__device__ __nv_bfloat16 g_w_lo[11 * HDIM * HDIM];

// ---------------- PTX helpers ----------------------------------------------
__device__ __forceinline__ uint32_t smem_to_u32(const void* p) {
    uint32_t a;
    asm("{ .reg .u64 t; cvta.to.shared.u64 t, %1; cvt.u32.u64 %0, t; }"
        : "=r"(a) : "l"(p));
    return a;
}
__device__ __forceinline__ void ldm_x4(uint32_t& r0, uint32_t& r1, uint32_t& r2,
                                       uint32_t& r3, uint32_t addr) {
    asm volatile("ldmatrix.sync.aligned.m8n8.x4.shared.b16 {%0,%1,%2,%3}, [%4];"
                 : "=r"(r0), "=r"(r1), "=r"(r2), "=r"(r3) : "r"(addr));
}
__device__ __forceinline__ void ldm_x2(uint32_t& r0, uint32_t& r1, uint32_t addr) {
    asm volatile("ldmatrix.sync.aligned.m8n8.x2.shared.b16 {%0,%1}, [%2];"
                 : "=r"(r0), "=r"(r1) : "r"(addr));
}
__device__ __forceinline__ void mma16816(float* c, const uint32_t* a, const uint32_t* b) {
    asm volatile(
        "mma.sync.aligned.m16n8k16.row.col.f32.bf16.bf16.f32 "
        "{%0,%1,%2,%3}, {%4,%5,%6,%7}, {%8,%9}, {%0,%1,%2,%3};"
        : "+f"(c[0]), "+f"(c[1]), "+f"(c[2]), "+f"(c[3])
        : "r"(a[0]), "r"(a[1]), "r"(a[2]), "r"(a[3]), "r"(b[0]), "r"(b[1]));
}

// swizzled smem offset: 128B rows, 16B chunks, SW128 (chunk ^= row&7)
__device__ __forceinline__ uint32_t swz(uint32_t row, uint32_t chunk) {
    return row * 128u + ((chunk ^ (row & 7u)) << 4);
}

// smem layout (dynamic, 64KB)
#define SM_AH 0
#define SM_AL 16384
#define SM_BH 32768
#define SM_BL 49152
#define SMEM_MMA 65536

// ---------------- split-bf16 tensor-core GEMM ------------------------------
// C[M,256] = A @ W + bias, A = a_hi + a_lo (bf16), W^T = wt (n-major [256,256]).
// BM=128, BN=128, K-chunks of 64; 8 warps as 2(m)x4(n): warp tile 64x32.
// acc += Ah*Bh + Ah*Bl + Al*Bh  (lo*lo dropped: ~1e-5 rel error)
__global__ void __launch_bounds__(256, 2) mma_gemm(
    const __nv_bfloat16* __restrict__ a_hi, const __nv_bfloat16* __restrict__ a_lo,
    const __nv_bfloat16* __restrict__ wt_hi, const __nv_bfloat16* __restrict__ wt_lo,
    const float* __restrict__ bias, float* __restrict__ C, int M)
{
    extern __shared__ char smem[];
    const uint32_t sb = smem_to_u32(smem);
    const int tid = threadIdx.x;
    const int lane = tid & 31;
    const int w = tid >> 5;
    const int bm = blockIdx.x * 128;
    const int bn = blockIdx.y * 128;
    const int wm = (w & 1) * 64;     // warp m-origin within tile
    const int wn = (w >> 1) * 32;    // warp n-origin within tile

    float c[4][4][4];
#pragma unroll
    for (int mt = 0; mt < 4; ++mt)
#pragma unroll
        for (int nt = 0; nt < 4; ++nt)
#pragma unroll
            for (int i = 0; i < 4; ++i) c[mt][nt][i] = 0.f;

    const int r8  = lane & 7;
    const int sub = lane >> 3;          // 0..3 (for x4)
    const int bsub = (lane >> 3) & 1;   // for x2

    for (int cc = 0; cc < 4; ++cc) {
        // ---- load 4 tiles (A hi/lo 128x64, B hi/lo 128x64 bf16) ----
#pragma unroll
        for (int j = 0; j < 4; ++j) {
            int i = tid + j * 256;         // 0..1023
            int r = i >> 3, ch = i & 7;
            int grow = bm + r; if (grow >= M) grow = M - 1;
            uint32_t so = swz((uint32_t)r, (uint32_t)ch);
            const uint4* pah = (const uint4*)(a_hi + (size_t)grow * HDIM + cc * 64);
            const uint4* pal = (const uint4*)(a_lo + (size_t)grow * HDIM + cc * 64);
            *(uint4*)(smem + SM_AH + so) = pah[ch];
            *(uint4*)(smem + SM_AL + so) = pal[ch];
            int nrow = bn + r;             // always < 256
            const uint4* pbh = (const uint4*)(wt_hi + (size_t)nrow * HDIM + cc * 64);
            const uint4* pbl = (const uint4*)(wt_lo + (size_t)nrow * HDIM + cc * 64);
            *(uint4*)(smem + SM_BH + so) = pbh[ch];
            *(uint4*)(smem + SM_BL + so) = pbl[ch];
        }
        __syncthreads();

#pragma unroll
        for (int s = 0; s < 4; ++s) {     // k16 steps within the 64-chunk
            // A-hi fragments (4 m-tiles)
            uint32_t ah[4][4];
#pragma unroll
            for (int mt = 0; mt < 4; ++mt) {
                uint32_t row = (uint32_t)(wm + mt * 16 + r8 + (sub & 1) * 8);
                uint32_t chunk = (uint32_t)(s * 2 + (sub >> 1));
                ldm_x4(ah[mt][0], ah[mt][1], ah[mt][2], ah[mt][3],
                       sb + SM_AH + swz(row, chunk));
            }
            // B-hi fragments (4 n-tiles)
            uint32_t bh[4][2];
#pragma unroll
            for (int nt = 0; nt < 4; ++nt) {
                uint32_t row = (uint32_t)(wn + nt * 8 + r8);
                uint32_t chunk = (uint32_t)(s * 2 + bsub);
                ldm_x2(bh[nt][0], bh[nt][1], sb + SM_BH + swz(row, chunk));
            }
#pragma unroll
            for (int mt = 0; mt < 4; ++mt)
#pragma unroll
                for (int nt = 0; nt < 4; ++nt)
                    mma16816(c[mt][nt], ah[mt], bh[nt]);

            // B-lo fragments: Ah * Bl
            uint32_t bl[4][2];
#pragma unroll
            for (int nt = 0; nt < 4; ++nt) {
                uint32_t row = (uint32_t)(wn + nt * 8 + r8);
                uint32_t chunk = (uint32_t)(s * 2 + bsub);
                ldm_x2(bl[nt][0], bl[nt][1], sb + SM_BL + swz(row, chunk));
            }
#pragma unroll
            for (int mt = 0; mt < 4; ++mt)
#pragma unroll
                for (int nt = 0; nt < 4; ++nt)
                    mma16816(c[mt][nt], ah[mt], bl[nt]);

            // A-lo fragments: Al * Bh
            uint32_t al[4][4];
#pragma unroll
            for (int mt = 0; mt < 4; ++mt) {
                uint32_t row = (uint32_t)(wm + mt * 16 + r8 + (sub & 1) * 8);
                uint32_t chunk = (uint32_t)(s * 2 + (sub >> 1));
                ldm_x4(al[mt][0], al[mt][1], al[mt][2], al[mt][3],
                       sb + SM_AL + swz(row, chunk));
            }
#pragma unroll
            for (int mt = 0; mt < 4; ++mt)
#pragma unroll
                for (int nt = 0; nt < 4; ++nt)
                    mma16816(c[mt][nt], al[mt], bh[nt]);
        }
        __syncthreads();
    }

    // ---- epilogue: c fragments + bias -> gmem ----
    const int g = lane >> 2, tg = lane & 3;
#pragma unroll
    for (int mt = 0; mt < 4; ++mt) {
#pragma unroll
        for (int nt = 0; nt < 4; ++nt) {
            int row0 = bm + wm + mt * 16 + g;
            int col  = bn + wn + nt * 8 + tg * 2;
            float b0 = bias[col], b1 = bias[col + 1];
            if (row0 < M) {
                float2 o; o.x = c[mt][nt][0] + b0; o.y = c[mt][nt][1] + b1;
                *(float2*)(C + (size_t)row0 * HDIM + col) = o;
            }
            int row1 = row0 + 8;
            if (row1 < M) {
                float2 o; o.x = c[mt][nt][2] + b0; o.y = c[mt][nt][3] + b1;
                *(float2*)(C + (size_t)row1 * HDIM + col) = o;
            }
        }
    }
}

// ---------------- fp32 -> (hi, lo) bf16 split, optional 2-way combine ------
__global__ void __launch_bounds__(256) split_kernel(
    const float* __restrict__ a, const float* __restrict__ a2,
    const float* __restrict__ wsm,
    __nv_bfloat16* __restrict__ hi, __nv_bfloat16* __restrict__ lo, int n4)
{
    int i = blockIdx.x * blockDim.x + threadIdx.x;
    if (i >= n4) return;
    float w0 = 1.f, w1 = 0.f;
    if (wsm) {
        float x = wsm[0], y = wsm[1];
        float mx = fmaxf(x, y);
        float e0 = __expf(x - mx), e1 = __expf(y - mx);
        float inv = 1.f / (e0 + e1);
        w0 = e0 * inv; w1 = e1 * inv;
    }
    float4 v = ((const float4*)a)[i];
    if (a2) {
        float4 u = ((const float4*)a2)[i];
        v.x = w0 * v.x + w1 * u.x; v.y = w0 * v.y + w1 * u.y;
        v.z = w0 * v.z + w1 * u.z; v.w = w0 * v.w + w1 * u.w;
    }
    __nv_bfloat16 h0 = __float2bfloat16(v.x), h1 = __float2bfloat16(v.y);
    __nv_bfloat16 h2 = __float2bfloat16(v.z), h3 = __float2bfloat16(v.w);
    __nv_bfloat16 l0 = __float2bfloat16(v.x - __bfloat162float(h0));
    __nv_bfloat16 l1 = __float2bfloat16(v.y - __bfloat162float(h1));
    __nv_bfloat16 l2 = __float2bfloat16(v.z - __bfloat162float(h2));
    __nv_bfloat16 l3 = __float2bfloat16(v.w - __bfloat162float(h3));
    __nv_bfloat162* hp = (__nv_bfloat162*)(hi + (size_t)i * 4);
    __nv_bfloat162* lp = (__nv_bfloat162*)(lo + (size_t)i * 4);
    hp[0] = __nv_bfloat162(h0, h1); hp[1] = __nv_bfloat162(h2, h3);
    lp[0] = __nv_bfloat162(l0, l1); lp[1] = __nv_bfloat162(l2, l3);
}

// ---------------- weight transpose + split: Wt[n,k] = W[k,n] ---------------
__global__ void __launch_bounds__(256) wsplit_kernel(
    const float* __restrict__ W,
    __nv_bfloat16* __restrict__ hi, __nv_bfloat16* __restrict__ lo)
{
    int i = blockIdx.x * blockDim.x + threadIdx.x;   // i = n*256 + k
    int n = i >> 8, k = i & 255;
    float v = W[k * HDIM + n];
    __nv_bfloat16 h = __float2bfloat16(v);
    hi[i] = h;
    lo[i] = __float2bfloat16(v - __bfloat162float(h));
}

// ---------------- segment offsets from sorted dst --------------------------
__global__ void __launch_bounds__(256) build_offsets(
    const int* __restrict__ dst, int* __restrict__ offs, int n_dst, int E)
{
    int e = blockIdx.x * blockDim.x + threadIdx.x;
    if (e >= E) return;
    int d = dst[e];
    if (e == 0) {
        for (int k = 0; k <= d; ++k) offs[k] = 0;
    } else {
        int dp = dst[e - 1];
        for (int k = dp + 1; k <= d; ++k) offs[k] = e;
    }
    if (e == E - 1) {
        for (int k = d + 1; k <= n_dst; ++k) offs[k] = E;
    }
}

// ---------------- edge attention scores: warp per edge ---------------------
__global__ void __launch_bounds__(256) edge_attn_kernel(
    const float* __restrict__ q, const float* __restrict__ k,
    const int* __restrict__ src, const int* __restrict__ dst,
    const float* __restrict__ eattn, float* __restrict__ attn, int E)
{
    int e = (blockIdx.x * blockDim.x + threadIdx.x) >> 5;
    int lane = threadIdx.x & 31;
    if (e >= E) return;
    int s = src[e], d = dst[e];
    const float4* qp = (const float4*)(q + (size_t)d * HDIM) + lane * 2;
    const float4* kp = (const float4*)(k + (size_t)s * HDIM) + lane * 2;
    float4 q0 = qp[0], q1 = qp[1];
    float4 k0 = kp[0], k1 = kp[1];
    float p = q0.x * k0.x + q0.y * k0.y + q0.z * k0.z + q0.w * k0.w +
              q1.x * k1.x + q1.y * k1.y + q1.z * k1.z + q1.w * k1.w;
    p += __shfl_xor_sync(0xffffffffu, p, 1);
    p += __shfl_xor_sync(0xffffffffu, p, 2);
    if ((lane & 3) == 0) {
        int h = lane >> 2;
        attn[(size_t)e * NHEADS + h] = p * 0.17677669529663687f + eattn[h];
    }
}

// ---------------- segmented softmax + V aggregation: warp per dst node -----
__global__ void __launch_bounds__(256) seg_agg_kernel(
    const float* __restrict__ attn, const float* __restrict__ v,
    const int* __restrict__ src, const int* __restrict__ offs,
    float* __restrict__ out, int n_dst)
{
    int node = (blockIdx.x * blockDim.x + threadIdx.x) >> 5;
    int lane = threadIdx.x & 31;
    if (node >= n_dst) return;

    int lo = offs[node];
    int hi = offs[node + 1];

    const int h8 = lane & 7;
    const int head = lane >> 2;

    float m = 0.f;
    for (int e = lo; e < hi; ++e)
        m = fmaxf(m, attn[(size_t)e * NHEADS + h8]);

    float s = 0.f;
    float acc[8] = {0.f, 0.f, 0.f, 0.f, 0.f, 0.f, 0.f, 0.f};

    float a_cur = 0.f;
    float4 x0 = make_float4(0.f, 0.f, 0.f, 0.f);
    float4 x1 = make_float4(0.f, 0.f, 0.f, 0.f);
    if (lo < hi) {
        a_cur = attn[(size_t)lo * NHEADS + h8];
        const float4* vp = (const float4*)(v + (size_t)src[lo] * HDIM) + lane * 2;
        x0 = vp[0]; x1 = vp[1];
    }
    for (int e = lo; e < hi; ++e) {
        int en = e + 1;
        float a_nxt = 0.f;
        float4 y0 = make_float4(0.f, 0.f, 0.f, 0.f);
        float4 y1 = make_float4(0.f, 0.f, 0.f, 0.f);
        if (en < hi) {
            a_nxt = attn[(size_t)en * NHEADS + h8];
            const float4* vp = (const float4*)(v + (size_t)src[en] * HDIM) + lane * 2;
            y0 = vp[0]; y1 = vp[1];
        }
        float ev = __expf(a_cur - m);
        s += ev;
        float w = __shfl_sync(0xffffffffu, ev, head);
        acc[0] += w * x0.x; acc[1] += w * x0.y; acc[2] += w * x0.z; acc[3] += w * x0.w;
        acc[4] += w * x1.x; acc[5] += w * x1.y; acc[6] += w * x1.z; acc[7] += w * x1.w;
        a_cur = a_nxt; x0 = y0; x1 = y1;
    }
    float sh = __shfl_sync(0xffffffffu, s, head);
    float inv = 1.f / fmaxf(sh, 1e-9f);

    float* op = out + (size_t)node * HDIM + lane * 8;
    *(float4*)op       = make_float4(acc[0] * inv, acc[1] * inv, acc[2] * inv, acc[3] * inv);
    *(float4*)(op + 4) = make_float4(acc[4] * inv, acc[5] * inv, acc[6] * inv, acc[7] * inv);
}

// ---------------- residual + LayerNorm: warp per row -----------------------
__global__ void __launch_bounds__(256) ln_kernel(
    const float* __restrict__ x, const float* __restrict__ t,
    const float* __restrict__ g, const float* __restrict__ b,
    float* __restrict__ out, int M)
{
    int row = (blockIdx.x * blockDim.x + threadIdx.x) >> 5;
    int lane = threadIdx.x & 31;
    if (row >= M) return;

    const float4* xp = (const float4*)(x + (size_t)row * HDIM) + lane * 2;
    const float4* tp = (const float4*)(t + (size_t)row * HDIM) + lane * 2;
    float4 a0 = xp[0], a1 = xp[1], c0 = tp[0], c1 = tp[1];
    float vals[8];
    vals[0] = a0.x + c0.x; vals[1] = a0.y + c0.y; vals[2] = a0.z + c0.z; vals[3] = a0.w + c0.w;
    vals[4] = a1.x + c1.x; vals[5] = a1.y + c1.y; vals[6] = a1.z + c1.z; vals[7] = a1.w + c1.w;

    float sum = 0.f, sq = 0.f;
#pragma unroll
    for (int j = 0; j < 8; ++j) { sum += vals[j]; sq += vals[j] * vals[j]; }
#pragma unroll
    for (int o = 16; o; o >>= 1) {
        sum += __shfl_xor_sync(0xffffffffu, sum, o);
        sq  += __shfl_xor_sync(0xffffffffu, sq,  o);
    }
    float mean = sum * (1.f / HDIM);
    float var  = sq * (1.f / HDIM) - mean * mean;
    float inv  = rsqrtf(var + 1e-5f);

    const float4* gp = (const float4*)(g) + lane * 2;
    const float4* bp = (const float4*)(b) + lane * 2;
    float4 g0 = gp[0], g1 = gp[1], bb0 = bp[0], bb1 = bp[1];

    float* op = out + (size_t)row * HDIM + lane * 8;
    float4 o0, o1;
    o0.x = (vals[0] - mean) * inv * g0.x + bb0.x;
    o0.y = (vals[1] - mean) * inv * g0.y + bb0.y;
    o0.z = (vals[2] - mean) * inv * g0.z + bb0.z;
    o0.w = (vals[3] - mean) * inv * g0.w + bb0.w;
    o1.x = (vals[4] - mean) * inv * g1.x + bb1.x;
    o1.y = (vals[5] - mean) * inv * g1.y + bb1.y;
    o1.z = (vals[6] - mean) * inv * g1.z + bb1.z;
    o1.w = (vals[7] - mean) * inv * g1.w + bb1.w;
    *(float4*)op       = o0;
    *(float4*)(op + 4) = o1;
}

// ---------------------------------------------------------------------------
extern "C" void kernel_launch(void* const* d_in, const int* in_sizes, int n_in,
                              void* d_out, int out_size)
{
    const float* x_paper  = (const float*)d_in[0];
    const float* x_author = (const float*)d_in[1];
    const int* w_src  = (const int*)d_in[2];
    const int* w_dst  = (const int*)d_in[3];
    const int* wr_src = (const int*)d_in[4];
    const int* wr_dst = (const int*)d_in[5];
    const int* c_src  = (const int*)d_in[6];
    const int* c_dst  = (const int*)d_in[7];
    const float* Wq = (const float*)d_in[8];
    const float* bq = (const float*)d_in[9];
    const float* Wk = (const float*)d_in[10];
    const float* bk = (const float*)d_in[11];
    const float* Wv = (const float*)d_in[12];
    const float* bv = (const float*)d_in[13];
    const float* eattn = (const float*)d_in[14];
    const float* Wout_p = (const float*)d_in[15];
    const float* bout_p = (const float*)d_in[16];
    const float* Wout_a = (const float*)d_in[17];
    const float* bout_a = (const float*)d_in[18];
    const float* lng_p = (const float*)d_in[19];
    const float* lnb_p = (const float*)d_in[20];
    const float* lng_a = (const float*)d_in[21];
    const float* lnb_a = (const float*)d_in[22];
    const float* w_paper = (const float*)d_in[23];

    float* out = (float*)d_out;

    float *q0, *k0, *v0, *q1, *k1, *v1, *q2, *k2, *v2;
    float *at0, *at1, *at2, *aw, *awr, *ac, *tp, *ta;
    int *of0, *of1, *of2;
    __nv_bfloat16 *xph, *xpl, *xah, *xal, *cbh, *cbl, *arh, *arl, *wh, *wl;
    cudaGetSymbolAddress((void**)&q0, g_q0);
    cudaGetSymbolAddress((void**)&k0, g_k0);
    cudaGetSymbolAddress((void**)&v0, g_v0);
    cudaGetSymbolAddress((void**)&q1, g_q1);
    cudaGetSymbolAddress((void**)&k1, g_k1);
    cudaGetSymbolAddress((void**)&v1, g_v1);
    cudaGetSymbolAddress((void**)&q2, g_q2);
    cudaGetSymbolAddress((void**)&k2, g_k2);
    cudaGetSymbolAddress((void**)&v2, g_v2);
    cudaGetSymbolAddress((void**)&at0, g_attn0);
    cudaGetSymbolAddress((void**)&at1, g_attn1);
    cudaGetSymbolAddress((void**)&at2, g_attn2);
    cudaGetSymbolAddress((void**)&aw, g_aggw);
    cudaGetSymbolAddress((void**)&awr, g_aggwr);
    cudaGetSymbolAddress((void**)&ac, g_aggc);
    cudaGetSymbolAddress((void**)&tp, g_tmp_p);
    cudaGetSymbolAddress((void**)&ta, g_tmp_a);
    cudaGetSymbolAddress((void**)&of0, g_offs0);
    cudaGetSymbolAddress((void**)&of1, g_offs1);
    cudaGetSymbolAddress((void**)&of2, g_offs2);
    cudaGetSymbolAddress((void**)&xph, g_xp_hi);
    cudaGetSymbolAddress((void**)&xpl, g_xp_lo);
    cudaGetSymbolAddress((void**)&xah, g_xa_hi);
    cudaGetSymbolAddress((void**)&xal, g_xa_lo);
    cudaGetSymbolAddress((void**)&cbh, g_cb_hi);
    cudaGetSymbolAddress((void**)&cbl, g_cb_lo);
    cudaGetSymbolAddress((void**)&arh, g_ar_hi);
    cudaGetSymbolAddress((void**)&arl, g_ar_lo);
    cudaGetSymbolAddress((void**)&wh, g_w_hi);
    cudaGetSymbolAddress((void**)&wl, g_w_lo);

    cudaFuncSetAttribute(mma_gemm, cudaFuncAttributeMaxDynamicSharedMemorySize, SMEM_MMA);

    const int HH = HDIM * HDIM;

    auto mm = [&](const __nv_bfloat16* ah, const __nv_bfloat16* al, int widx,
                  const float* bias, float* C, int M) {
        dim3 grid((M + 127) / 128, HDIM / 128);
        mma_gemm<<<grid, 256, SMEM_MMA>>>(
            ah, al, wh + (size_t)widx * HH, wl + (size_t)widx * HH, bias, C, M);
    };

    // ---- weight + input conversions (main stream) ----
    const float* Wsrc[11] = {Wq + 0*HH, Wk + 0*HH, Wv + 0*HH,
                             Wq + 1*HH, Wk + 1*HH, Wv + 1*HH,
                             Wq + 2*HH, Wk + 2*HH, Wv + 2*HH,
                             Wout_p, Wout_a};
    for (int i = 0; i < 11; ++i)
        wsplit_kernel<<<HH / 256, 256>>>(Wsrc[i], wh + (size_t)i * HH, wl + (size_t)i * HH);
    split_kernel<<<(NPAPER * HDIM / 4 + 255) / 256, 256>>>(
        x_paper, nullptr, nullptr, xph, xpl, NPAPER * HDIM / 4);
    split_kernel<<<(NAUTHOR * HDIM / 4 + 255) / 256, 256>>>(
        x_author, nullptr, nullptr, xah, xal, NAUTHOR * HDIM / 4);

    // ---- side stream + fork/join events (created per call; not destroyed
    // while capture is in progress) ----
    cudaStream_t s2;
    cudaStreamCreateWithFlags(&s2, cudaStreamNonBlocking);
    cudaEvent_t evStart, evA, evB, evC, evDone;
    cudaEventCreateWithFlags(&evStart, cudaEventDisableTiming);
    cudaEventCreateWithFlags(&evA,     cudaEventDisableTiming);
    cudaEventCreateWithFlags(&evB,     cudaEventDisableTiming);
    cudaEventCreateWithFlags(&evC,     cudaEventDisableTiming);
    cudaEventCreateWithFlags(&evDone,  cudaEventDisableTiming);

    cudaEventRecord(evStart, 0);
    cudaStreamWaitEvent(s2, evStart, 0);

    // side stream: offset builds
    int oblocks = (NEDGE + 255) / 256;
    build_offsets<<<oblocks, 256, 0, s2>>>(w_dst,  of0, NPAPER,  NEDGE);
    build_offsets<<<oblocks, 256, 0, s2>>>(wr_dst, of1, NAUTHOR, NEDGE);
    build_offsets<<<oblocks, 256, 0, s2>>>(c_dst,  of2, NPAPER,  NEDGE);

    // main: rel-0 projections
    mm(xph, xpl, 0, bq + 0 * HDIM, q0, NPAPER);
    mm(xah, xal, 1, bk + 0 * HDIM, k0, NAUTHOR);
    mm(xah, xal, 2, bv + 0 * HDIM, v0, NAUTHOR);
    cudaEventRecord(evA, 0);

    // main: rel-1 projections
    mm(xah, xal, 3, bq + 1 * HDIM, q1, NAUTHOR);
    mm(xph, xpl, 4, bk + 1 * HDIM, k1, NPAPER);
    mm(xph, xpl, 5, bv + 1 * HDIM, v1, NPAPER);
    cudaEventRecord(evB, 0);

    // main: rel-2 projections
    mm(xph, xpl, 6, bq + 2 * HDIM, q2, NPAPER);
    mm(xph, xpl, 7, bk + 2 * HDIM, k2, NPAPER);
    mm(xph, xpl, 8, bv + 2 * HDIM, v2, NPAPER);
    cudaEventRecord(evC, 0);

    // side stream: per-relation edge phase + output-operand splits
    int eblocks = (NEDGE * 32 + 255) / 256;
    cudaStreamWaitEvent(s2, evA, 0);
    edge_attn_kernel<<<eblocks, 256, 0, s2>>>(q0, k0, w_src,  w_dst,  eattn + 0,  at0, NEDGE);
    seg_agg_kernel<<<(NPAPER * 32 + 255) / 256, 256, 0, s2>>>(at0, v0, w_src,  of0, aw,  NPAPER);
    cudaStreamWaitEvent(s2, evB, 0);
    edge_attn_kernel<<<eblocks, 256, 0, s2>>>(q1, k1, wr_src, wr_dst, eattn + 8,  at1, NEDGE);
    seg_agg_kernel<<<(NAUTHOR * 32 + 255) / 256, 256, 0, s2>>>(at1, v1, wr_src, of1, awr, NAUTHOR);
    split_kernel<<<(NAUTHOR * HDIM / 4 + 255) / 256, 256, 0, s2>>>(
        awr, nullptr, nullptr, arh, arl, NAUTHOR * HDIM / 4);
    cudaStreamWaitEvent(s2, evC, 0);
    edge_attn_kernel<<<eblocks, 256, 0, s2>>>(q2, k2, c_src,  c_dst,  eattn + 16, at2, NEDGE);
    seg_agg_kernel<<<(NPAPER * 32 + 255) / 256, 256, 0, s2>>>(at2, v2, c_src,  of2, ac,  NPAPER);
    split_kernel<<<(NPAPER * HDIM / 4 + 255) / 256, 256, 0, s2>>>(
        aw, ac, w_paper, cbh, cbl, NPAPER * HDIM / 4);
    cudaEventRecord(evDone, s2);

    // join
    cudaStreamWaitEvent(0, evDone, 0);

    // output projections
    mm(cbh, cbl, 9,  bout_p, tp, NPAPER);
    mm(arh, arl, 10, bout_a, ta, NAUTHOR);

    // residual + layernorm -> packed output [paper | author]
    ln_kernel<<<(NPAPER * 32 + 255) / 256, 256>>>(x_paper, tp, lng_p, lnb_p, out, NPAPER);
    ln_kernel<<<(NAUTHOR * 32 + 255) / 256, 256>>>(x_author, ta, lng_a, lnb_a,
                                                   out + (size_t)NPAPER * HDIM, NAUTHOR);
}

// round 17
// speedup vs baseline: 2.1196x; 1.0423x over previous
#include <cuda_runtime.h>
#include <cuda_bf16.h>
#include <math.h>
#include <stdint.h>

#define NPAPER  100000
#define NAUTHOR 50000
#define NEDGE   400000
#define HDIM    256
#define NHEADS  8
#define HD      32

// ---------------- scratch (device globals; no allocation allowed) ----------
__device__ float g_q0[NPAPER * HDIM];
__device__ float g_k0[NAUTHOR * HDIM];
__device__ float g_v0[NAUTHOR * HDIM];
__device__ float g_q1[NAUTHOR * HDIM];
__device__ float g_k1[NPAPER * HDIM];
__device__ float g_v1[NPAPER * HDIM];
__device__ float g_q2[NPAPER * HDIM];
__device__ float g_k2[NPAPER * HDIM];
__device__ float g_v2[NPAPER * HDIM];
__device__ float g_attn0[NEDGE * NHEADS];
__device__ float g_attn1[NEDGE * NHEADS];
__device__ float g_attn2[NEDGE * NHEADS];
__device__ float g_aggw[NPAPER * HDIM];
__device__ float g_aggwr[NAUTHOR * HDIM];
__device__ float g_aggc[NPAPER * HDIM];
__device__ float g_tmp_p[NPAPER * HDIM];
__device__ float g_tmp_a[NAUTHOR * HDIM];
__device__ int   g_offs0[NPAPER + 1];
__device__ int   g_offs1[NAUTHOR + 1];
__device__ int   g_offs2[NPAPER + 1];

// split-bf16 operands
__device__ __nv_bfloat16 g_xp_hi[NPAPER * HDIM];
__device__ __nv_bfloat16 g_xp_lo[NPAPER * HDIM];
__device__ __nv_bfloat16 g_xa_hi[NAUTHOR * HDIM];
__device__ __nv_bfloat16 g_xa_lo[NAUTHOR * HDIM];
__device__ __nv_bfloat16 g_cb_hi[NPAPER * HDIM];
__device__ __nv_bfloat16 g_cb_lo[NPAPER * HDIM];
__device__ __nv_bfloat16 g_ar_hi[NAUTHOR * HDIM];
__device__ __nv_bfloat16 g_ar_lo[NAUTHOR * HDIM];
__device__ __nv_bfloat16 g_w_hi[11 * HDIM * HDIM];
__device__ __nv_bfloat16 g_w_lo[11 * HDIM * HDIM];

// ---------------- PTX helpers ----------------------------------------------
__device__ __forceinline__ uint32_t smem_to_u32(const void* p) {
    uint32_t a;
    asm("{ .reg .u64 t; cvta.to.shared.u64 t, %1; cvt.u32.u64 %0, t; }"
        : "=r"(a) : "l"(p));
    return a;
}
__device__ __forceinline__ void ldm_x4(uint32_t& r0, uint32_t& r1, uint32_t& r2,
                                       uint32_t& r3, uint32_t addr) {
    asm volatile("ldmatrix.sync.aligned.m8n8.x4.shared.b16 {%0,%1,%2,%3}, [%4];"
                 : "=r"(r0), "=r"(r1), "=r"(r2), "=r"(r3) : "r"(addr));
}
__device__ __forceinline__ void ldm_x2(uint32_t& r0, uint32_t& r1, uint32_t addr) {
    asm volatile("ldmatrix.sync.aligned.m8n8.x2.shared.b16 {%0,%1}, [%2];"
                 : "=r"(r0), "=r"(r1) : "r"(addr));
}
__device__ __forceinline__ void mma16816(float* c, const uint32_t* a, const uint32_t* b) {
    asm volatile(
        "mma.sync.aligned.m16n8k16.row.col.f32.bf16.bf16.f32 "
        "{%0,%1,%2,%3}, {%4,%5,%6,%7}, {%8,%9}, {%0,%1,%2,%3};"
        : "+f"(c[0]), "+f"(c[1]), "+f"(c[2]), "+f"(c[3])
        : "r"(a[0]), "r"(a[1]), "r"(a[2]), "r"(a[3]), "r"(b[0]), "r"(b[1]));
}

// swizzled smem offset: 128B rows, 16B chunks, SW128 (chunk ^= row&7)
__device__ __forceinline__ uint32_t swz(uint32_t row, uint32_t chunk) {
    return row * 128u + ((chunk ^ (row & 7u)) << 4);
}

// smem layout (dynamic, 64KB)
#define SM_AH 0
#define SM_AL 16384
#define SM_BH 32768
#define SM_BL 49152
#define SMEM_MMA 65536

// ---------------- split-bf16 tensor-core GEMM ------------------------------
// C[M,256] = A @ W + bias, A = a_hi + a_lo (bf16), W^T = wt (n-major [256,256]).
// BM=128, BN=128, K-chunks of 64; 8 warps as 2(m)x4(n): warp tile 64x32.
// acc += Ah*Bh + Ah*Bl + Al*Bh  (lo*lo dropped: ~2e-6 rel error)
__global__ void __launch_bounds__(256, 2) mma_gemm(
    const __nv_bfloat16* __restrict__ a_hi, const __nv_bfloat16* __restrict__ a_lo,
    const __nv_bfloat16* __restrict__ wt_hi, const __nv_bfloat16* __restrict__ wt_lo,
    const float* __restrict__ bias, float* __restrict__ C, int M)
{
    extern __shared__ char smem[];
    const uint32_t sb = smem_to_u32(smem);
    const int tid = threadIdx.x;
    const int lane = tid & 31;
    const int w = tid >> 5;
    const int bm = blockIdx.x * 128;
    const int bn = blockIdx.y * 128;
    const int wm = (w & 1) * 64;
    const int wn = (w >> 1) * 32;

    float c[4][4][4];
#pragma unroll
    for (int mt = 0; mt < 4; ++mt)
#pragma unroll
        for (int nt = 0; nt < 4; ++nt)
#pragma unroll
            for (int i = 0; i < 4; ++i) c[mt][nt][i] = 0.f;

    const int r8  = lane & 7;
    const int sub = lane >> 3;
    const int bsub = (lane >> 3) & 1;

    for (int cc = 0; cc < 4; ++cc) {
#pragma unroll
        for (int j = 0; j < 4; ++j) {
            int i = tid + j * 256;
            int r = i >> 3, ch = i & 7;
            int grow = bm + r; if (grow >= M) grow = M - 1;
            uint32_t so = swz((uint32_t)r, (uint32_t)ch);
            const uint4* pah = (const uint4*)(a_hi + (size_t)grow * HDIM + cc * 64);
            const uint4* pal = (const uint4*)(a_lo + (size_t)grow * HDIM + cc * 64);
            *(uint4*)(smem + SM_AH + so) = pah[ch];
            *(uint4*)(smem + SM_AL + so) = pal[ch];
            int nrow = bn + r;
            const uint4* pbh = (const uint4*)(wt_hi + (size_t)nrow * HDIM + cc * 64);
            const uint4* pbl = (const uint4*)(wt_lo + (size_t)nrow * HDIM + cc * 64);
            *(uint4*)(smem + SM_BH + so) = pbh[ch];
            *(uint4*)(smem + SM_BL + so) = pbl[ch];
        }
        __syncthreads();

#pragma unroll
        for (int s = 0; s < 4; ++s) {
            uint32_t ah[4][4];
#pragma unroll
            for (int mt = 0; mt < 4; ++mt) {
                uint32_t row = (uint32_t)(wm + mt * 16 + r8 + (sub & 1) * 8);
                uint32_t chunk = (uint32_t)(s * 2 + (sub >> 1));
                ldm_x4(ah[mt][0], ah[mt][1], ah[mt][2], ah[mt][3],
                       sb + SM_AH + swz(row, chunk));
            }
            uint32_t bh[4][2];
#pragma unroll
            for (int nt = 0; nt < 4; ++nt) {
                uint32_t row = (uint32_t)(wn + nt * 8 + r8);
                uint32_t chunk = (uint32_t)(s * 2 + bsub);
                ldm_x2(bh[nt][0], bh[nt][1], sb + SM_BH + swz(row, chunk));
            }
#pragma unroll
            for (int mt = 0; mt < 4; ++mt)
#pragma unroll
                for (int nt = 0; nt < 4; ++nt)
                    mma16816(c[mt][nt], ah[mt], bh[nt]);

            uint32_t bl[4][2];
#pragma unroll
            for (int nt = 0; nt < 4; ++nt) {
                uint32_t row = (uint32_t)(wn + nt * 8 + r8);
                uint32_t chunk = (uint32_t)(s * 2 + bsub);
                ldm_x2(bl[nt][0], bl[nt][1], sb + SM_BL + swz(row, chunk));
            }
#pragma unroll
            for (int mt = 0; mt < 4; ++mt)
#pragma unroll
                for (int nt = 0; nt < 4; ++nt)
                    mma16816(c[mt][nt], ah[mt], bl[nt]);

            uint32_t al[4][4];
#pragma unroll
            for (int mt = 0; mt < 4; ++mt) {
                uint32_t row = (uint32_t)(wm + mt * 16 + r8 + (sub & 1) * 8);
                uint32_t chunk = (uint32_t)(s * 2 + (sub >> 1));
                ldm_x4(al[mt][0], al[mt][1], al[mt][2], al[mt][3],
                       sb + SM_AL + swz(row, chunk));
            }
#pragma unroll
            for (int mt = 0; mt < 4; ++mt)
#pragma unroll
                for (int nt = 0; nt < 4; ++nt)
                    mma16816(c[mt][nt], al[mt], bh[nt]);
        }
        __syncthreads();
    }

    const int g = lane >> 2, tg = lane & 3;
#pragma unroll
    for (int mt = 0; mt < 4; ++mt) {
#pragma unroll
        for (int nt = 0; nt < 4; ++nt) {
            int row0 = bm + wm + mt * 16 + g;
            int col  = bn + wn + nt * 8 + tg * 2;
            float b0 = bias[col], b1 = bias[col + 1];
            if (row0 < M) {
                float2 o; o.x = c[mt][nt][0] + b0; o.y = c[mt][nt][1] + b1;
                *(float2*)(C + (size_t)row0 * HDIM + col) = o;
            }
            int row1 = row0 + 8;
            if (row1 < M) {
                float2 o; o.x = c[mt][nt][2] + b0; o.y = c[mt][nt][3] + b1;
                *(float2*)(C + (size_t)row1 * HDIM + col) = o;
            }
        }
    }
}

// ---------------- fp32 -> (hi, lo) bf16 split, optional 2-way combine ------
__global__ void __launch_bounds__(256) split_kernel(
    const float* __restrict__ a, const float* __restrict__ a2,
    const float* __restrict__ wsm,
    __nv_bfloat16* __restrict__ hi, __nv_bfloat16* __restrict__ lo, int n4)
{
    int i = blockIdx.x * blockDim.x + threadIdx.x;
    if (i >= n4) return;
    float w0 = 1.f, w1 = 0.f;
    if (wsm) {
        float x = wsm[0], y = wsm[1];
        float mx = fmaxf(x, y);
        float e0 = __expf(x - mx), e1 = __expf(y - mx);
        float inv = 1.f / (e0 + e1);
        w0 = e0 * inv; w1 = e1 * inv;
    }
    float4 v = ((const float4*)a)[i];
    if (a2) {
        float4 u = ((const float4*)a2)[i];
        v.x = w0 * v.x + w1 * u.x; v.y = w0 * v.y + w1 * u.y;
        v.z = w0 * v.z + w1 * u.z; v.w = w0 * v.w + w1 * u.w;
    }
    __nv_bfloat16 h0 = __float2bfloat16(v.x), h1 = __float2bfloat16(v.y);
    __nv_bfloat16 h2 = __float2bfloat16(v.z), h3 = __float2bfloat16(v.w);
    __nv_bfloat16 l0 = __float2bfloat16(v.x - __bfloat162float(h0));
    __nv_bfloat16 l1 = __float2bfloat16(v.y - __bfloat162float(h1));
    __nv_bfloat16 l2 = __float2bfloat16(v.z - __bfloat162float(h2));
    __nv_bfloat16 l3 = __float2bfloat16(v.w - __bfloat162float(h3));
    __nv_bfloat162* hp = (__nv_bfloat162*)(hi + (size_t)i * 4);
    __nv_bfloat162* lp = (__nv_bfloat162*)(lo + (size_t)i * 4);
    hp[0] = __nv_bfloat162(h0, h1); hp[1] = __nv_bfloat162(h2, h3);
    lp[0] = __nv_bfloat162(l0, l1); lp[1] = __nv_bfloat162(l2, l3);
}

// ---------------- ALL weight transposes + splits in one launch -------------
// widx = blockIdx.y: 0..8 = rel r=widx/3, type widx%3 (0=q,1=k,2=v); 9=out_p; 10=out_a
__global__ void __launch_bounds__(256) wsplit_all(
    const float* __restrict__ Wq, const float* __restrict__ Wk,
    const float* __restrict__ Wv, const float* __restrict__ Wop,
    const float* __restrict__ Woa,
    __nv_bfloat16* __restrict__ hi, __nv_bfloat16* __restrict__ lo)
{
    const int HH = HDIM * HDIM;
    int widx = blockIdx.y;
    const float* W;
    if (widx < 9) {
        int r = widx / 3, t = widx - r * 3;
        W = (t == 0 ? Wq : (t == 1 ? Wk : Wv)) + r * HH;
    } else {
        W = (widx == 9) ? Wop : Woa;
    }
    int i = blockIdx.x * blockDim.x + threadIdx.x;   // i = n*256 + k
    int n = i >> 8, k = i & 255;
    float v = W[k * HDIM + n];
    __nv_bfloat16 h = __float2bfloat16(v);
    hi[(size_t)widx * HH + i] = h;
    lo[(size_t)widx * HH + i] = __float2bfloat16(v - __bfloat162float(h));
}

// ---------------- segment offsets from sorted dst --------------------------
__global__ void __launch_bounds__(256) build_offsets(
    const int* __restrict__ dst, int* __restrict__ offs, int n_dst, int E)
{
    int e = blockIdx.x * blockDim.x + threadIdx.x;
    if (e >= E) return;
    int d = dst[e];
    if (e == 0) {
        for (int k = 0; k <= d; ++k) offs[k] = 0;
    } else {
        int dp = dst[e - 1];
        for (int k = dp + 1; k <= d; ++k) offs[k] = e;
    }
    if (e == E - 1) {
        for (int k = d + 1; k <= n_dst; ++k) offs[k] = E;
    }
}

// ---------------- edge attention scores: warp per edge ---------------------
__global__ void __launch_bounds__(256) edge_attn_kernel(
    const float* __restrict__ q, const float* __restrict__ k,
    const int* __restrict__ src, const int* __restrict__ dst,
    const float* __restrict__ eattn, float* __restrict__ attn, int E)
{
    int e = (blockIdx.x * blockDim.x + threadIdx.x) >> 5;
    int lane = threadIdx.x & 31;
    if (e >= E) return;
    int s = src[e], d = dst[e];
    const float4* qp = (const float4*)(q + (size_t)d * HDIM) + lane * 2;
    const float4* kp = (const float4*)(k + (size_t)s * HDIM) + lane * 2;
    float4 q0 = qp[0], q1 = qp[1];
    float4 k0 = kp[0], k1 = kp[1];
    float p = q0.x * k0.x + q0.y * k0.y + q0.z * k0.z + q0.w * k0.w +
              q1.x * k1.x + q1.y * k1.y + q1.z * k1.z + q1.w * k1.w;
    p += __shfl_xor_sync(0xffffffffu, p, 1);
    p += __shfl_xor_sync(0xffffffffu, p, 2);
    if ((lane & 3) == 0) {
        int h = lane >> 2;
        attn[(size_t)e * NHEADS + h] = p * 0.17677669529663687f + eattn[h];
    }
}

// ---------------- segmented softmax + V aggregation: warp per dst node -----
__global__ void __launch_bounds__(256) seg_agg_kernel(
    const float* __restrict__ attn, const float* __restrict__ v,
    const int* __restrict__ src, const int* __restrict__ offs,
    float* __restrict__ out, int n_dst)
{
    int node = (blockIdx.x * blockDim.x + threadIdx.x) >> 5;
    int lane = threadIdx.x & 31;
    if (node >= n_dst) return;

    int lo = offs[node];
    int hi = offs[node + 1];

    const int h8 = lane & 7;
    const int head = lane >> 2;

    float m = 0.f;
    for (int e = lo; e < hi; ++e)
        m = fmaxf(m, attn[(size_t)e * NHEADS + h8]);

    float s = 0.f;
    float acc[8] = {0.f, 0.f, 0.f, 0.f, 0.f, 0.f, 0.f, 0.f};

    float a_cur = 0.f;
    float4 x0 = make_float4(0.f, 0.f, 0.f, 0.f);
    float4 x1 = make_float4(0.f, 0.f, 0.f, 0.f);
    if (lo < hi) {
        a_cur = attn[(size_t)lo * NHEADS + h8];
        const float4* vp = (const float4*)(v + (size_t)src[lo] * HDIM) + lane * 2;
        x0 = vp[0]; x1 = vp[1];
    }
    for (int e = lo; e < hi; ++e) {
        int en = e + 1;
        float a_nxt = 0.f;
        float4 y0 = make_float4(0.f, 0.f, 0.f, 0.f);
        float4 y1 = make_float4(0.f, 0.f, 0.f, 0.f);
        if (en < hi) {
            a_nxt = attn[(size_t)en * NHEADS + h8];
            const float4* vp = (const float4*)(v + (size_t)src[en] * HDIM) + lane * 2;
            y0 = vp[0]; y1 = vp[1];
        }
        float ev = __expf(a_cur - m);
        s += ev;
        float w = __shfl_sync(0xffffffffu, ev, head);
        acc[0] += w * x0.x; acc[1] += w * x0.y; acc[2] += w * x0.z; acc[3] += w * x0.w;
        acc[4] += w * x1.x; acc[5] += w * x1.y; acc[6] += w * x1.z; acc[7] += w * x1.w;
        a_cur = a_nxt; x0 = y0; x1 = y1;
    }
    float sh = __shfl_sync(0xffffffffu, s, head);
    float inv = 1.f / fmaxf(sh, 1e-9f);

    float* op = out + (size_t)node * HDIM + lane * 8;
    *(float4*)op       = make_float4(acc[0] * inv, acc[1] * inv, acc[2] * inv, acc[3] * inv);
    *(float4*)(op + 4) = make_float4(acc[4] * inv, acc[5] * inv, acc[6] * inv, acc[7] * inv);
}

// ---------------- residual + LayerNorm: warp per row -----------------------
__global__ void __launch_bounds__(256) ln_kernel(
    const float* __restrict__ x, const float* __restrict__ t,
    const float* __restrict__ g, const float* __restrict__ b,
    float* __restrict__ out, int M)
{
    int row = (blockIdx.x * blockDim.x + threadIdx.x) >> 5;
    int lane = threadIdx.x & 31;
    if (row >= M) return;

    const float4* xp = (const float4*)(x + (size_t)row * HDIM) + lane * 2;
    const float4* tp = (const float4*)(t + (size_t)row * HDIM) + lane * 2;
    float4 a0 = xp[0], a1 = xp[1], c0 = tp[0], c1 = tp[1];
    float vals[8];
    vals[0] = a0.x + c0.x; vals[1] = a0.y + c0.y; vals[2] = a0.z + c0.z; vals[3] = a0.w + c0.w;
    vals[4] = a1.x + c1.x; vals[5] = a1.y + c1.y; vals[6] = a1.z + c1.z; vals[7] = a1.w + c1.w;

    float sum = 0.f, sq = 0.f;
#pragma unroll
    for (int j = 0; j < 8; ++j) { sum += vals[j]; sq += vals[j] * vals[j]; }
#pragma unroll
    for (int o = 16; o; o >>= 1) {
        sum += __shfl_xor_sync(0xffffffffu, sum, o);
        sq  += __shfl_xor_sync(0xffffffffu, sq,  o);
    }
    float mean = sum * (1.f / HDIM);
    float var  = sq * (1.f / HDIM) - mean * mean;
    float inv  = rsqrtf(var + 1e-5f);

    const float4* gp = (const float4*)(g) + lane * 2;
    const float4* bp = (const float4*)(b) + lane * 2;
    float4 g0 = gp[0], g1 = gp[1], bb0 = bp[0], bb1 = bp[1];

    float* op = out + (size_t)row * HDIM + lane * 8;
    float4 o0, o1;
    o0.x = (vals[0] - mean) * inv * g0.x + bb0.x;
    o0.y = (vals[1] - mean) * inv * g0.y + bb0.y;
    o0.z = (vals[2] - mean) * inv * g0.z + bb0.z;
    o0.w = (vals[3] - mean) * inv * g0.w + bb0.w;
    o1.x = (vals[4] - mean) * inv * g1.x + bb1.x;
    o1.y = (vals[5] - mean) * inv * g1.y + bb1.y;
    o1.z = (vals[6] - mean) * inv * g1.z + bb1.z;
    o1.w = (vals[7] - mean) * inv * g1.w + bb1.w;
    *(float4*)op       = o0;
    *(float4*)(op + 4) = o1;
}

// ---------------------------------------------------------------------------
extern "C" void kernel_launch(void* const* d_in, const int* in_sizes, int n_in,
                              void* d_out, int out_size)
{
    const float* x_paper  = (const float*)d_in[0];
    const float* x_author = (const float*)d_in[1];
    const int* w_src  = (const int*)d_in[2];
    const int* w_dst  = (const int*)d_in[3];
    const int* wr_src = (const int*)d_in[4];
    const int* wr_dst = (const int*)d_in[5];
    const int* c_src  = (const int*)d_in[6];
    const int* c_dst  = (const int*)d_in[7];
    const float* Wq = (const float*)d_in[8];
    const float* bq = (const float*)d_in[9];
    const float* Wk = (const float*)d_in[10];
    const float* bk = (const float*)d_in[11];
    const float* Wv = (const float*)d_in[12];
    const float* bv = (const float*)d_in[13];
    const float* eattn = (const float*)d_in[14];
    const float* Wout_p = (const float*)d_in[15];
    const float* bout_p = (const float*)d_in[16];
    const float* Wout_a = (const float*)d_in[17];
    const float* bout_a = (const float*)d_in[18];
    const float* lng_p = (const float*)d_in[19];
    const float* lnb_p = (const float*)d_in[20];
    const float* lng_a = (const float*)d_in[21];
    const float* lnb_a = (const float*)d_in[22];
    const float* w_paper = (const float*)d_in[23];

    float* out = (float*)d_out;

    float *q0, *k0, *v0, *q1, *k1, *v1, *q2, *k2, *v2;
    float *at0, *at1, *at2, *aw, *awr, *ac, *tp, *ta;
    int *of0, *of1, *of2;
    __nv_bfloat16 *xph, *xpl, *xah, *xal, *cbh, *cbl, *arh, *arl, *wh, *wl;
    cudaGetSymbolAddress((void**)&q0, g_q0);
    cudaGetSymbolAddress((void**)&k0, g_k0);
    cudaGetSymbolAddress((void**)&v0, g_v0);
    cudaGetSymbolAddress((void**)&q1, g_q1);
    cudaGetSymbolAddress((void**)&k1, g_k1);
    cudaGetSymbolAddress((void**)&v1, g_v1);
    cudaGetSymbolAddress((void**)&q2, g_q2);
    cudaGetSymbolAddress((void**)&k2, g_k2);
    cudaGetSymbolAddress((void**)&v2, g_v2);
    cudaGetSymbolAddress((void**)&at0, g_attn0);
    cudaGetSymbolAddress((void**)&at1, g_attn1);
    cudaGetSymbolAddress((void**)&at2, g_attn2);
    cudaGetSymbolAddress((void**)&aw, g_aggw);
    cudaGetSymbolAddress((void**)&awr, g_aggwr);
    cudaGetSymbolAddress((void**)&ac, g_aggc);
    cudaGetSymbolAddress((void**)&tp, g_tmp_p);
    cudaGetSymbolAddress((void**)&ta, g_tmp_a);
    cudaGetSymbolAddress((void**)&of0, g_offs0);
    cudaGetSymbolAddress((void**)&of1, g_offs1);
    cudaGetSymbolAddress((void**)&of2, g_offs2);
    cudaGetSymbolAddress((void**)&xph, g_xp_hi);
    cudaGetSymbolAddress((void**)&xpl, g_xp_lo);
    cudaGetSymbolAddress((void**)&xah, g_xa_hi);
    cudaGetSymbolAddress((void**)&xal, g_xa_lo);
    cudaGetSymbolAddress((void**)&cbh, g_cb_hi);
    cudaGetSymbolAddress((void**)&cbl, g_cb_lo);
    cudaGetSymbolAddress((void**)&arh, g_ar_hi);
    cudaGetSymbolAddress((void**)&arl, g_ar_lo);
    cudaGetSymbolAddress((void**)&wh, g_w_hi);
    cudaGetSymbolAddress((void**)&wl, g_w_lo);

    cudaFuncSetAttribute(mma_gemm, cudaFuncAttributeMaxDynamicSharedMemorySize, SMEM_MMA);

    const int HH = HDIM * HDIM;

    auto mm = [&](cudaStream_t st, const __nv_bfloat16* ah, const __nv_bfloat16* al,
                  int widx, const float* bias, float* C, int M) {
        dim3 grid((M + 127) / 128, HDIM / 128);
        mma_gemm<<<grid, 256, SMEM_MMA, st>>>(
            ah, al, wh + (size_t)widx * HH, wl + (size_t)widx * HH, bias, C, M);
    };

    // ---- conversions (main stream): one batched weight split + 2 input splits
    {
        dim3 wg(HH / 256, 11);
        wsplit_all<<<wg, 256>>>(Wq, Wk, Wv, Wout_p, Wout_a, wh, wl);
    }
    split_kernel<<<(NPAPER * HDIM / 4 + 255) / 256, 256>>>(
        x_paper, nullptr, nullptr, xph, xpl, NPAPER * HDIM / 4);
    split_kernel<<<(NAUTHOR * HDIM / 4 + 255) / 256, 256>>>(
        x_author, nullptr, nullptr, xah, xal, NAUTHOR * HDIM / 4);

    // ---- side stream + events (created per call; not destroyed during capture)
    cudaStream_t s2;
    cudaStreamCreateWithFlags(&s2, cudaStreamNonBlocking);
    cudaEvent_t evStart, evQK[3], evV[3], evCb, evS2done;
    cudaEventCreateWithFlags(&evStart, cudaEventDisableTiming);
    for (int r = 0; r < 3; ++r) {
        cudaEventCreateWithFlags(&evQK[r], cudaEventDisableTiming);
        cudaEventCreateWithFlags(&evV[r],  cudaEventDisableTiming);
    }
    cudaEventCreateWithFlags(&evCb,     cudaEventDisableTiming);
    cudaEventCreateWithFlags(&evS2done, cudaEventDisableTiming);

    cudaEventRecord(evStart, 0);
    cudaStreamWaitEvent(s2, evStart, 0);

    // side stream: offset builds
    int oblocks = (NEDGE + 255) / 256;
    build_offsets<<<oblocks, 256, 0, s2>>>(w_dst,  of0, NPAPER,  NEDGE);
    build_offsets<<<oblocks, 256, 0, s2>>>(wr_dst, of1, NAUTHOR, NEDGE);
    build_offsets<<<oblocks, 256, 0, s2>>>(c_dst,  of2, NPAPER,  NEDGE);

    // main: projections, q/k first then v, per-relation events
    // rel 0 (widx 0=q0 paper, 1=k0 author, 2=v0 author)
    mm(0, xph, xpl, 0, bq + 0 * HDIM, q0, NPAPER);
    mm(0, xah, xal, 1, bk + 0 * HDIM, k0, NAUTHOR);
    cudaEventRecord(evQK[0], 0);
    mm(0, xah, xal, 2, bv + 0 * HDIM, v0, NAUTHOR);
    cudaEventRecord(evV[0], 0);
    // rel 1 (3=q1 author, 4=k1 paper, 5=v1 paper)
    mm(0, xah, xal, 3, bq + 1 * HDIM, q1, NAUTHOR);
    mm(0, xph, xpl, 4, bk + 1 * HDIM, k1, NPAPER);
    cudaEventRecord(evQK[1], 0);
    mm(0, xph, xpl, 5, bv + 1 * HDIM, v1, NPAPER);
    cudaEventRecord(evV[1], 0);
    // rel 2 (6=q2, 7=k2, 8=v2, all paper)
    mm(0, xph, xpl, 6, bq + 2 * HDIM, q2, NPAPER);
    mm(0, xph, xpl, 7, bk + 2 * HDIM, k2, NPAPER);
    cudaEventRecord(evQK[2], 0);
    mm(0, xph, xpl, 8, bv + 2 * HDIM, v2, NPAPER);
    cudaEventRecord(evV[2], 0);

    // side stream: edge phase; edge_attn_r overlaps v_r GEMM
    int eblocks = (NEDGE * 32 + 255) / 256;
    cudaStreamWaitEvent(s2, evQK[0], 0);
    edge_attn_kernel<<<eblocks, 256, 0, s2>>>(q0, k0, w_src,  w_dst,  eattn + 0,  at0, NEDGE);
    cudaStreamWaitEvent(s2, evV[0], 0);
    seg_agg_kernel<<<(NPAPER * 32 + 255) / 256, 256, 0, s2>>>(at0, v0, w_src,  of0, aw,  NPAPER);
    cudaStreamWaitEvent(s2, evQK[1], 0);
    edge_attn_kernel<<<eblocks, 256, 0, s2>>>(q1, k1, wr_src, wr_dst, eattn + 8,  at1, NEDGE);
    cudaStreamWaitEvent(s2, evV[1], 0);
    seg_agg_kernel<<<(NAUTHOR * 32 + 255) / 256, 256, 0, s2>>>(at1, v1, wr_src, of1, awr, NAUTHOR);
    cudaStreamWaitEvent(s2, evQK[2], 0);
    edge_attn_kernel<<<eblocks, 256, 0, s2>>>(q2, k2, c_src,  c_dst,  eattn + 16, at2, NEDGE);
    cudaStreamWaitEvent(s2, evV[2], 0);
    seg_agg_kernel<<<(NPAPER * 32 + 255) / 256, 256, 0, s2>>>(at2, v2, c_src,  of2, ac,  NPAPER);

    // side stream: cb split (needs aw + ac) -> signal main for paper out
    split_kernel<<<(NPAPER * HDIM / 4 + 255) / 256, 256, 0, s2>>>(
        aw, ac, w_paper, cbh, cbl, NPAPER * HDIM / 4);
    cudaEventRecord(evCb, s2);

    // side stream: author chain (concurrent with main's paper-out GEMM)
    split_kernel<<<(NAUTHOR * HDIM / 4 + 255) / 256, 256, 0, s2>>>(
        awr, nullptr, nullptr, arh, arl, NAUTHOR * HDIM / 4);
    mm(s2, arh, arl, 10, bout_a, ta, NAUTHOR);
    ln_kernel<<<(NAUTHOR * 32 + 255) / 256, 256, 0, s2>>>(
        x_author, ta, lng_a, lnb_a, out + (size_t)NPAPER * HDIM, NAUTHOR);
    cudaEventRecord(evS2done, s2);

    // main: paper output path
    cudaStreamWaitEvent(0, evCb, 0);
    mm(0, cbh, cbl, 9, bout_p, tp, NPAPER);
    ln_kernel<<<(NPAPER * 32 + 255) / 256, 256>>>(x_paper, tp, lng_p, lnb_p, out, NPAPER);

    // join side stream before capture ends
    cudaStreamWaitEvent(0, evS2done, 0);
}